// round 6
// baseline (speedup 1.0000x reference)
#include <cuda_runtime.h>

#define NB   4
#define DC   256
#define HH   64
#define WW   64
#define HW   4096
#define DCH  16       // chunks over D (pass 1)
#define DPER 16       // D per chunk (pass 1)
#define NOFF 12
#define TY   8        // rows per tile (pass 1 / pass 3)
#define HALO 11       // TY + 3 halo rows (dy in -1..2)
#define WTY  4        // rows per k_weights tile
#define WHALO 7
#define DSLICE 4      // d-slices per pipeline stage
#define ODC  16       // d-chunks for k_output
#define ODPER 16      // d per k_output block

// offset order: 3x3 window row-major (idx 4 = (0,0)), then (-1,2),(2,-1),(2,2).
__device__ __constant__ int c_dy[NOFF] = {-1,-1,-1, 0,0,0, 1,1,1, -1, 2, 2};
__device__ __constant__ int c_dx[NOFF] = {-1, 0, 1,-1,0,1,-1,0,1,  2,-1, 2};

// scratch (no allocations allowed)
__device__ __align__(16) float g_part[(size_t)NB * DCH * 14 * HW];   // 14.7 MB
__device__ __align__(16) float g_w0[NB * HW];
__device__ __align__(16) float g_w1[NB * HW];
__device__ __align__(16) float g_w2[NB * HW];
__device__ __align__(16) float g_w3[NB * HW];
__device__ __align__(16) float g_cond[NB * HW];

__device__ __forceinline__ int iclamp(int v, int lo, int hi) {
    return v < lo ? lo : (v > hi ? hi : v);
}

__device__ __forceinline__ void cp_async16(void* dst, const void* src) {
    unsigned int da = (unsigned int)__cvta_generic_to_shared(dst);
    asm volatile("cp.async.cg.shared.global [%0], [%1], 16;" :: "r"(da), "l"(src));
}
__device__ __forceinline__ void cp_commit() {
    asm volatile("cp.async.commit_group;");
}
template <int N>
__device__ __forceinline__ void cp_wait() {
    asm volatile("cp.async.wait_group %0;" :: "n"(N));
}

#define PREV_F (DSLICE * HALO * WW)     // 2816 floats
#define CUR_F  (DSLICE * TY * WW)       // 2048 floats
#define TOT_Q  ((PREV_F + CUR_F) / 4)   // 1216 float4 per buffer

// ---------------------------------------------------------------------------
// Pass 1: cp.async double-buffered, 2 pixels/thread with vector LDS.
// grid (8 ytiles, 16 dchunks, 4 batch) = 512 blocks, block (32, 8) = 256 thr
// ---------------------------------------------------------------------------
__global__ __launch_bounds__(256) void k_partial(const float* __restrict__ cur,
                                                 const float* __restrict__ prev) {
    __shared__ float sp[2][PREV_F];   // 22.5 KB
    __shared__ float sc[2][CUR_F];    // 16 KB

    const int tx  = threadIdx.x;           // 0..31 -> pixels 2tx, 2tx+1
    const int ty  = threadIdx.y;           // 0..7
    const int y0  = blockIdx.x * TY;
    const int dch = blockIdx.y;
    const int n   = blockIdx.z;
    const int tid = ty * 32 + tx;          // 0..255
    const int x0  = tx * 2;

    const float* curB  = cur  + (size_t)n * DC * HW;
    const float* prevB = prev + (size_t)n * DC * HW;
    const int d0 = dch * DPER;

    auto stage = [&](int b, int dbase) {
#pragma unroll
        for (int j = 0; j < 5; j++) {
            const int i = tid + j * 256;
            if (i < PREV_F / 4) {                    // prev: 704 float4
                const int s  = i / (HALO * 16);
                const int rm = i - s * (HALO * 16);
                const int r  = rm >> 4;
                const int c4 = rm & 15;
                const int gr = iclamp(y0 - 1 + r, 0, HH - 1);
                cp_async16(&sp[b][s * (HALO * WW) + r * WW + c4 * 4],
                           prevB + (size_t)(dbase + s) * HW + gr * WW + c4 * 4);
            } else if (i < TOT_Q) {                  // cur: 512 float4
                const int k  = i - PREV_F / 4;
                const int s  = k >> 7;               // 128 float4 per slice
                const int rm = k & 127;
                const int r  = rm >> 4;
                const int c4 = rm & 15;
                cp_async16(&sc[b][s * (TY * WW) + r * WW + c4 * 4],
                           curB + (size_t)(dbase + s) * HW + (y0 + r) * WW + c4 * 4);
            }
        }
        cp_commit();
    };

    const int rA = (ty    ) * WW;   // dy=-1
    const int rB = (ty + 1) * WW;   // dy= 0
    const int rC = (ty + 2) * WW;   // dy=+1
    const int rD = (ty + 3) * WW;   // dy=+2
    const int xl  = x0 == 0 ? 0 : x0 - 1;
    const int xr2 = x0 + 2 > WW - 1 ? WW - 1 : x0 + 2;
    const bool lastx = (tx == 31);

    float2 acc[14];
#pragma unroll
    for (int k = 0; k < 14; k++) acc[k] = make_float2(0.f, 0.f);

    stage(0, d0);

#pragma unroll 1
    for (int d4 = 0; d4 < DPER / DSLICE; d4++) {
        if (d4 + 1 < DPER / DSLICE) {
            stage((d4 + 1) & 1, d0 + (d4 + 1) * DSLICE);
            cp_wait<1>();
        } else {
            cp_wait<0>();
        }
        __syncthreads();

        const int b = d4 & 1;
#pragma unroll
        for (int s = 0; s < DSLICE; s++) {
            const float* P = sp[b] + s * (HALO * WW);
            const float2 c2 = *(const float2*)&sc[b][s * (TY * WW) + ty * WW + x0];

            const float2 A0 = *(const float2*)&P[rA + x0];
            const float2 B0 = *(const float2*)&P[rB + x0];
            const float2 C0 = *(const float2*)&P[rC + x0];
            const float2 D0 = *(const float2*)&P[rD + x0];
            const float  AL = P[rA + xl];
            const float  BL = P[rB + xl];
            const float  CL = P[rC + xl];
            const float  DL = P[rD + xl];
            const float2 A1 = lastx ? make_float2(A0.y, A0.y)
                                    : *(const float2*)&P[rA + x0 + 2];
            const float2 D1 = lastx ? make_float2(D0.y, D0.y)
                                    : *(const float2*)&P[rD + x0 + 2];
            const float  B2 = P[rB + xr2];
            const float  C2 = P[rC + xr2];

            const float c0 = c2.x, c1 = c2.y;
            acc[0].x  = fmaf(c0, AL,   acc[0].x);   acc[0].y  = fmaf(c1, A0.x, acc[0].y);
            acc[1].x  = fmaf(c0, A0.x, acc[1].x);   acc[1].y  = fmaf(c1, A0.y, acc[1].y);
            acc[2].x  = fmaf(c0, A0.y, acc[2].x);   acc[2].y  = fmaf(c1, A1.x, acc[2].y);
            acc[3].x  = fmaf(c0, BL,   acc[3].x);   acc[3].y  = fmaf(c1, B0.x, acc[3].y);
            acc[4].x  = fmaf(c0, B0.x, acc[4].x);   acc[4].y  = fmaf(c1, B0.y, acc[4].y);
            acc[5].x  = fmaf(c0, B0.y, acc[5].x);   acc[5].y  = fmaf(c1, B2,   acc[5].y);
            acc[6].x  = fmaf(c0, CL,   acc[6].x);   acc[6].y  = fmaf(c1, C0.x, acc[6].y);
            acc[7].x  = fmaf(c0, C0.x, acc[7].x);   acc[7].y  = fmaf(c1, C0.y, acc[7].y);
            acc[8].x  = fmaf(c0, C0.y, acc[8].x);   acc[8].y  = fmaf(c1, C2,   acc[8].y);
            acc[9].x  = fmaf(c0, A1.x, acc[9].x);   acc[9].y  = fmaf(c1, A1.y, acc[9].y);
            acc[10].x = fmaf(c0, DL,   acc[10].x);  acc[10].y = fmaf(c1, D0.x, acc[10].y);
            acc[11].x = fmaf(c0, D1.x, acc[11].x);  acc[11].y = fmaf(c1, D1.y, acc[11].y);
            acc[12].x = fmaf(c0, c0,   acc[12].x);  acc[12].y = fmaf(c1, c1,   acc[12].y);
            acc[13].x = fmaf(B0.x, B0.x, acc[13].x);
            acc[13].y = fmaf(B0.y, B0.y, acc[13].y);
        }
        __syncthreads();
    }

    const int pix = (y0 + ty) * WW + x0;
    float* o = g_part + (size_t)(n * DCH + dch) * 14 * HW + pix;
#pragma unroll
    for (int k = 0; k < 14; k++) *(float2*)&o[(size_t)k * HW] = acc[k];
}

// ---------------------------------------------------------------------------
// Pass 2: chunk-reduce (in-kernel) + cosine affinity -> cond + 4 agg weights.
// grid (16, NB), block (64, 4). g_part is L2-resident. All loads coalesced.
// ---------------------------------------------------------------------------
__global__ __launch_bounds__(256) void k_weights() {
    __shared__ float s_pn[WHALO * WW];

    const int x   = threadIdx.x;
    const int ty  = threadIdx.y;
    const int y0  = blockIdx.x * WTY;
    const int n   = blockIdx.y;
    const int tid = ty * WW + x;

    const float* base = g_part + (size_t)n * DCH * 14 * HW;

    // halo prev-norms (slot 13 reduced over chunks)
    for (int i = tid; i < WHALO * WW; i += 256) {
        const int r  = i >> 6;
        const int cc = i & (WW - 1);
        const int gr = iclamp(y0 - 1 + r, 0, HH - 1);
        const int gp = gr * WW + cc;
        float s = 0.f;
#pragma unroll
        for (int c = 0; c < DCH; c++)
            s += base[((size_t)c * 14 + 13) * HW + gp];
        s_pn[i] = sqrtf(s) + 1e-8f;
    }
    __syncthreads();

    const int y   = y0 + ty;
    const int pix = y * WW + x;

    float acc[13];
#pragma unroll
    for (int k = 0; k < 13; k++) acc[k] = 0.f;
#pragma unroll
    for (int c = 0; c < DCH; c++) {
        const float* b = base + (size_t)c * 14 * HW + pix;
#pragma unroll
        for (int k = 0; k < 13; k++) acc[k] += b[(size_t)k * HW];
    }

    const float invcn = 1.f / (sqrtf(acc[12]) + 1e-8f);

    float aff[NOFF];
#pragma unroll
    for (int k = 0; k < NOFF; k++) {
        const int py = y + c_dy[k];
        const int px = x + c_dx[k];
        const bool valid = (py >= 0) & (py < HH) & (px >= 0) & (px < WW);
        const int lr = ty + c_dy[k] + 1;
        const int lc = iclamp(px, 0, WW - 1);
        const float pn = s_pn[lr * WW + lc];
        float a = acc[k] * invcn / pn;
        a = fmaxf(a, 0.f);
        aff[k] = valid ? a : 0.f;
    }

    float mass = 0.f;
#pragma unroll
    for (int k = 0; k < 9; k++) mass += aff[k];

    const bool  cond = (mass > -10.f) && (mass < 10.f);
    const float inv  = 1.f / (mass > 0.f ? mass : 1.f);

    const int t = n * HW + pix;
    g_w0[t]   = aff[0]  > 0.f ? aff[0]  * inv : 0.f;  // (-1,-1)
    g_w1[t]   = aff[9]  > 0.f ? aff[9]  * inv : 0.f;  // (-1,+2)
    g_w2[t]   = aff[10] > 0.f ? aff[10] * inv : 0.f;  // (+2,-1)
    g_w3[t]   = aff[11] > 0.f ? aff[11] * inv : 0.f;  // (+2,+2)
    g_cond[t] = cond ? 1.f : 0.f;
}

// ---------------------------------------------------------------------------
// Pass 3: cp.async double-buffered, smem-tiled output.
// grid (8 ytiles, 16 dchunks, 4 batch) = 512 blocks, block (32,8) = 256 thr
// ---------------------------------------------------------------------------
#define OMEM_F (DSLICE * HALO * WW)     // 2816 floats per buffer

__global__ __launch_bounds__(256) void k_output(const float* __restrict__ mem,
                                                float* __restrict__ out) {
    __shared__ float sm[2][OMEM_F];     // 22.5 KB

    const int tx  = threadIdx.x;           // 0..31 -> pixels 2tx, 2tx+1
    const int ty  = threadIdx.y;           // 0..7
    const int y0  = blockIdx.x * TY;
    const int dch = blockIdx.y;
    const int n   = blockIdx.z;
    const int tid = ty * 32 + tx;
    const int x0  = tx * 2;
    const int d0  = dch * ODPER;

    const float* memB = mem + (size_t)n * DC * HW;

    auto stage = [&](int b, int dbase) {
#pragma unroll
        for (int j = 0; j < 3; j++) {
            const int i = tid + j * 256;
            if (i < OMEM_F / 4) {                  // 704 float4
                const int s  = i / (HALO * 16);
                const int rm = i - s * (HALO * 16);
                const int r  = rm >> 4;
                const int c4 = rm & 15;
                const int gr = iclamp(y0 - 1 + r, 0, HH - 1);
                cp_async16(&sm[b][s * (HALO * WW) + r * WW + c4 * 4],
                           memB + (size_t)(dbase + s) * HW + gr * WW + c4 * 4);
            }
        }
        cp_commit();
    };

    // per-thread weights for its 2 pixels (once per block)
    const int y   = y0 + ty;
    const int np  = n * HW + y * WW + x0;
    const float2 cond = *(const float2*)&g_cond[np];
    const float2 w0   = *(const float2*)&g_w0[np];
    const float2 w1   = *(const float2*)&g_w1[np];
    const float2 w2   = *(const float2*)&g_w2[np];
    const float2 w3   = *(const float2*)&g_w3[np];

    const int rA = (ty    ) * WW;   // y-1
    const int rB = (ty + 1) * WW;   // y
    const int rD = (ty + 3) * WW;   // y+2
    const int xl = x0 == 0 ? 0 : x0 - 1;
    const bool lastx = (tx == 31);

    float* outB = out + ((size_t)n * DC + d0) * HW + y * WW + x0;

    stage(0, d0);

#pragma unroll 1
    for (int st = 0; st < ODPER / DSLICE; st++) {
        if (st + 1 < ODPER / DSLICE) {
            stage((st + 1) & 1, d0 + (st + 1) * DSLICE);
            cp_wait<1>();
        } else {
            cp_wait<0>();
        }
        __syncthreads();

        const int b = st & 1;
#pragma unroll
        for (int s = 0; s < DSLICE; s++) {
            const int d = d0 + st * DSLICE + s;
            const float* P = sm[b] + s * (HALO * WW);

            float2 v = *(const float2*)&P[rB + x0];

            if (d != 0) {
                const float AL  = P[rA + xl];
                const float A0x = P[rA + x0];
                const float2 A1 = lastx ? make_float2(A0x, A0x)
                                        : *(const float2*)&P[rA + x0 + 2];
                const float DL  = P[rD + xl];
                const float D0x = P[rD + x0];
                const float2 D1 = lastx ? make_float2(D0x, D0x)
                                        : *(const float2*)&P[rD + x0 + 2];
                v.x = fmaf(w0.x, AL,  fmaf(w1.x, A1.x, fmaf(w2.x, DL,  fmaf(w3.x, D1.x, v.x))));
                v.y = fmaf(w0.y, A0x, fmaf(w1.y, A1.y, fmaf(w2.y, D0x, fmaf(w3.y, D1.y, v.y))));
            }

            v.x = cond.x != 0.f ? v.x : 0.f;
            v.y = cond.y != 0.f ? v.y : 0.f;

            *(float2*)&outB[(size_t)(st * DSLICE + s) * HW] = v;
        }
        __syncthreads();
    }
}

// ---------------------------------------------------------------------------
extern "C" void kernel_launch(void* const* d_in, const int* in_sizes, int n_in,
                              void* d_out, int out_size) {
    const float* cur  = (const float*)d_in[0];
    const float* prev = (const float*)d_in[1];
    const float* mem  = (const float*)d_in[2];
    float* out = (float*)d_out;

    k_partial<<<dim3(HH / TY, DCH, NB), dim3(32, TY)>>>(cur, prev);
    k_weights<<<dim3(HH / WTY, NB), dim3(WW, WTY)>>>();
    k_output<<<dim3(HH / TY, ODC, NB), dim3(32, TY)>>>(mem, out);
}

// round 7
// speedup vs baseline: 1.2568x; 1.2568x over previous
#include <cuda_runtime.h>

#define NB   4
#define DC   256
#define HH   64
#define WW   64
#define HW   4096
#define DCH  8        // chunks over D (pass 1)
#define DPER 32       // D per chunk (pass 1)
#define NOFF 12
#define TY   4        // rows per tile
#define HALO 7        // TY + 3 halo rows (dy in -1..2)
#define DSLICE 4      // d-slices per pipeline stage (pass 1)
#define ODC  16       // d-chunks for k_output
#define ODPER 16      // d per k_output block
#define OSLICE 8      // d-slices per k_output stage

// offset order: 3x3 window row-major (idx 4 = (0,0)), then (-1,2),(2,-1),(2,2).
__device__ __constant__ int c_dy[NOFF] = {-1,-1,-1, 0,0,0, 1,1,1, -1, 2, 2};
__device__ __constant__ int c_dx[NOFF] = {-1, 0, 1,-1,0,1,-1,0,1,  2,-1, 2};

// scratch (no allocations allowed)
__device__ __align__(16) float g_part[(size_t)NB * DCH * 14 * HW];   // 7.3 MB
__device__ __align__(16) float g_w0[NB * HW];
__device__ __align__(16) float g_w1[NB * HW];
__device__ __align__(16) float g_w2[NB * HW];
__device__ __align__(16) float g_w3[NB * HW];
__device__ __align__(16) float g_cond[NB * HW];

__device__ __forceinline__ int iclamp(int v, int lo, int hi) {
    return v < lo ? lo : (v > hi ? hi : v);
}

__device__ __forceinline__ void cp_async16(void* dst, const void* src) {
    unsigned int da = (unsigned int)__cvta_generic_to_shared(dst);
    asm volatile("cp.async.cg.shared.global [%0], [%1], 16;" :: "r"(da), "l"(src));
}
__device__ __forceinline__ void cp_commit() {
    asm volatile("cp.async.commit_group;");
}
template <int N>
__device__ __forceinline__ void cp_wait() {
    asm volatile("cp.async.wait_group %0;" :: "n"(N));
}

#define PREV_F (DSLICE * HALO * WW)     // 1792 floats
#define CUR_F  (DSLICE * TY * WW)       // 1024 floats
#define TOT_Q  ((PREV_F + CUR_F) / 4)   // 704 float4 per buffer

// ---------------------------------------------------------------------------
// Pass 1: cp.async double-buffered, 2 pixels/thread with vector LDS.
// grid (16 ytiles, 8 dchunks, 4 batch), block (32, 4) = 128 thr
// ---------------------------------------------------------------------------
__global__ __launch_bounds__(128) void k_partial(const float* __restrict__ cur,
                                                 const float* __restrict__ prev) {
    __shared__ float sp[2][PREV_F];
    __shared__ float sc[2][CUR_F];

    const int tx  = threadIdx.x;           // 0..31 -> pixels 2tx, 2tx+1
    const int ty  = threadIdx.y;           // 0..3
    const int y0  = blockIdx.x * TY;
    const int dch = blockIdx.y;
    const int n   = blockIdx.z;
    const int tid = ty * 32 + tx;
    const int x0  = tx * 2;

    const float* curB  = cur  + (size_t)n * DC * HW;
    const float* prevB = prev + (size_t)n * DC * HW;
    const int d0 = dch * DPER;

    auto stage = [&](int b, int dbase) {
#pragma unroll
        for (int j = 0; j < 6; j++) {
            const int i = tid + j * 128;
            if (i < PREV_F / 4) {
                const int s  = i / (HALO * 16);
                const int rm = i - s * (HALO * 16);
                const int r  = rm >> 4;
                const int c4 = rm & 15;
                const int gr = iclamp(y0 - 1 + r, 0, HH - 1);
                cp_async16(&sp[b][s * (HALO * WW) + r * WW + c4 * 4],
                           prevB + (size_t)(dbase + s) * HW + gr * WW + c4 * 4);
            } else if (i < TOT_Q) {
                const int k  = i - PREV_F / 4;
                const int s  = k >> 6;
                const int rm = k & 63;
                const int r  = rm >> 4;
                const int c4 = rm & 15;
                cp_async16(&sc[b][s * (TY * WW) + r * WW + c4 * 4],
                           curB + (size_t)(dbase + s) * HW + (y0 + r) * WW + c4 * 4);
            }
        }
        cp_commit();
    };

    const int rA = (ty    ) * WW;   // dy=-1
    const int rB = (ty + 1) * WW;   // dy= 0
    const int rC = (ty + 2) * WW;   // dy=+1
    const int rD = (ty + 3) * WW;   // dy=+2
    const int xl  = x0 == 0 ? 0 : x0 - 1;
    const int xr2 = x0 + 2 > WW - 1 ? WW - 1 : x0 + 2;
    const bool lastx = (tx == 31);

    float2 acc[14];
#pragma unroll
    for (int k = 0; k < 14; k++) acc[k] = make_float2(0.f, 0.f);

    stage(0, d0);

#pragma unroll 1
    for (int d4 = 0; d4 < DPER / DSLICE; d4++) {
        if (d4 + 1 < DPER / DSLICE) {
            stage((d4 + 1) & 1, d0 + (d4 + 1) * DSLICE);
            cp_wait<1>();
        } else {
            cp_wait<0>();
        }
        __syncthreads();

        const int b = d4 & 1;
#pragma unroll
        for (int s = 0; s < DSLICE; s++) {
            const float* P = sp[b] + s * (HALO * WW);
            const float2 c2 = *(const float2*)&sc[b][s * (TY * WW) + ty * WW + x0];

            const float2 A0 = *(const float2*)&P[rA + x0];
            const float2 B0 = *(const float2*)&P[rB + x0];
            const float2 C0 = *(const float2*)&P[rC + x0];
            const float2 D0 = *(const float2*)&P[rD + x0];
            const float  AL = P[rA + xl];
            const float  BL = P[rB + xl];
            const float  CL = P[rC + xl];
            const float  DL = P[rD + xl];
            const float2 A1 = lastx ? make_float2(A0.y, A0.y)
                                    : *(const float2*)&P[rA + x0 + 2];
            const float2 D1 = lastx ? make_float2(D0.y, D0.y)
                                    : *(const float2*)&P[rD + x0 + 2];
            const float  B2 = P[rB + xr2];
            const float  C2 = P[rC + xr2];

            const float c0 = c2.x, c1 = c2.y;
            acc[0].x  = fmaf(c0, AL,   acc[0].x);   acc[0].y  = fmaf(c1, A0.x, acc[0].y);
            acc[1].x  = fmaf(c0, A0.x, acc[1].x);   acc[1].y  = fmaf(c1, A0.y, acc[1].y);
            acc[2].x  = fmaf(c0, A0.y, acc[2].x);   acc[2].y  = fmaf(c1, A1.x, acc[2].y);
            acc[3].x  = fmaf(c0, BL,   acc[3].x);   acc[3].y  = fmaf(c1, B0.x, acc[3].y);
            acc[4].x  = fmaf(c0, B0.x, acc[4].x);   acc[4].y  = fmaf(c1, B0.y, acc[4].y);
            acc[5].x  = fmaf(c0, B0.y, acc[5].x);   acc[5].y  = fmaf(c1, B2,   acc[5].y);
            acc[6].x  = fmaf(c0, CL,   acc[6].x);   acc[6].y  = fmaf(c1, C0.x, acc[6].y);
            acc[7].x  = fmaf(c0, C0.x, acc[7].x);   acc[7].y  = fmaf(c1, C0.y, acc[7].y);
            acc[8].x  = fmaf(c0, C0.y, acc[8].x);   acc[8].y  = fmaf(c1, C2,   acc[8].y);
            acc[9].x  = fmaf(c0, A1.x, acc[9].x);   acc[9].y  = fmaf(c1, A1.y, acc[9].y);
            acc[10].x = fmaf(c0, DL,   acc[10].x);  acc[10].y = fmaf(c1, D0.x, acc[10].y);
            acc[11].x = fmaf(c0, D1.x, acc[11].x);  acc[11].y = fmaf(c1, D1.y, acc[11].y);
            acc[12].x = fmaf(c0, c0,   acc[12].x);  acc[12].y = fmaf(c1, c1,   acc[12].y);
            acc[13].x = fmaf(B0.x, B0.x, acc[13].x);
            acc[13].y = fmaf(B0.y, B0.y, acc[13].y);
        }
        __syncthreads();
    }

    const int pix = (y0 + ty) * WW + x0;
    float* o = g_part + (size_t)(n * DCH + dch) * 14 * HW + pix;
#pragma unroll
    for (int k = 0; k < 14; k++) *(float2*)&o[(size_t)k * HW] = acc[k];
}

// ---------------------------------------------------------------------------
// Pass 2: in-kernel chunk-reduce + cosine affinity -> cond + 4 agg weights.
// grid (16, NB), block (64, 4). g_part is L2-resident; all loads coalesced.
// ---------------------------------------------------------------------------
__global__ __launch_bounds__(256) void k_weights() {
    __shared__ float s_pn[HALO * WW];

    const int x   = threadIdx.x;
    const int ty  = threadIdx.y;
    const int y0  = blockIdx.x * TY;
    const int n   = blockIdx.y;
    const int tid = ty * WW + x;

    const float* base = g_part + (size_t)n * DCH * 14 * HW;

    // halo prev-norms (slot 13 reduced over chunks)
    for (int i = tid; i < HALO * WW; i += 256) {
        const int r  = i >> 6;
        const int cc = i & (WW - 1);
        const int gr = iclamp(y0 - 1 + r, 0, HH - 1);
        const int gp = gr * WW + cc;
        float s = 0.f;
#pragma unroll
        for (int c = 0; c < DCH; c++)
            s += base[((size_t)c * 14 + 13) * HW + gp];
        s_pn[i] = sqrtf(s) + 1e-8f;
    }
    __syncthreads();

    const int y   = y0 + ty;
    const int pix = y * WW + x;

    float acc[13];
#pragma unroll
    for (int k = 0; k < 13; k++) acc[k] = 0.f;
#pragma unroll
    for (int c = 0; c < DCH; c++) {
        const float* b = base + (size_t)c * 14 * HW + pix;
#pragma unroll
        for (int k = 0; k < 13; k++) acc[k] += b[(size_t)k * HW];
    }

    const float invcn = 1.f / (sqrtf(acc[12]) + 1e-8f);

    float aff[NOFF];
#pragma unroll
    for (int k = 0; k < NOFF; k++) {
        const int py = y + c_dy[k];
        const int px = x + c_dx[k];
        const bool valid = (py >= 0) & (py < HH) & (px >= 0) & (px < WW);
        const int lr = ty + c_dy[k] + 1;
        const int lc = iclamp(px, 0, WW - 1);
        const float pn = s_pn[lr * WW + lc];
        float a = acc[k] * invcn / pn;
        a = fmaxf(a, 0.f);
        aff[k] = valid ? a : 0.f;
    }

    float mass = 0.f;
#pragma unroll
    for (int k = 0; k < 9; k++) mass += aff[k];

    const bool  cond = (mass > -10.f) && (mass < 10.f);
    const float inv  = 1.f / (mass > 0.f ? mass : 1.f);

    const int t = n * HW + pix;
    g_w0[t]   = aff[0]  > 0.f ? aff[0]  * inv : 0.f;  // (-1,-1)
    g_w1[t]   = aff[9]  > 0.f ? aff[9]  * inv : 0.f;  // (-1,+2)
    g_w2[t]   = aff[10] > 0.f ? aff[10] * inv : 0.f;  // (+2,-1)
    g_w3[t]   = aff[11] > 0.f ? aff[11] * inv : 0.f;  // (+2,+2)
    g_cond[t] = cond ? 1.f : 0.f;
}

// ---------------------------------------------------------------------------
// Pass 3: cp.async double-buffered, smem-tiled output. OSLICE=8 -> 2 stages,
// 4 barriers per block (was 8 stages / 16 barriers).
// grid (16 ytiles, 16 dchunks, 4 batch) = 1024 blocks, block (32,4) = 128 thr
// ---------------------------------------------------------------------------
#define OMEM_F (OSLICE * HALO * WW)     // 3584 floats per buffer (14.3 KB)

__global__ __launch_bounds__(128) void k_output(const float* __restrict__ mem,
                                                float* __restrict__ out) {
    __shared__ float sm[2][OMEM_F];     // 28.7 KB

    const int tx  = threadIdx.x;           // 0..31 -> pixels 2tx, 2tx+1
    const int ty  = threadIdx.y;           // 0..3
    const int y0  = blockIdx.x * TY;
    const int dch = blockIdx.y;
    const int n   = blockIdx.z;
    const int tid = ty * 32 + tx;
    const int x0  = tx * 2;
    const int d0  = dch * ODPER;

    const float* memB = mem + (size_t)n * DC * HW;

    auto stage = [&](int b, int dbase) {
#pragma unroll
        for (int j = 0; j < 7; j++) {          // 896 float4 / 128 threads
            const int i = tid + j * 128;
            const int s  = i / (HALO * 16);
            const int rm = i - s * (HALO * 16);
            const int r  = rm >> 4;
            const int c4 = rm & 15;
            const int gr = iclamp(y0 - 1 + r, 0, HH - 1);
            cp_async16(&sm[b][s * (HALO * WW) + r * WW + c4 * 4],
                       memB + (size_t)(dbase + s) * HW + gr * WW + c4 * 4);
        }
        cp_commit();
    };

    // per-thread weights for its 2 pixels (once per block)
    const int y   = y0 + ty;
    const int np  = n * HW + y * WW + x0;
    const float2 cond = *(const float2*)&g_cond[np];
    const float2 w0   = *(const float2*)&g_w0[np];
    const float2 w1   = *(const float2*)&g_w1[np];
    const float2 w2   = *(const float2*)&g_w2[np];
    const float2 w3   = *(const float2*)&g_w3[np];

    const int rA = (ty    ) * WW;   // y-1
    const int rB = (ty + 1) * WW;   // y
    const int rD = (ty + 3) * WW;   // y+2
    const int xl = x0 == 0 ? 0 : x0 - 1;
    const bool lastx = (tx == 31);

    float* outB = out + ((size_t)n * DC + d0) * HW + y * WW + x0;

    stage(0, d0);

#pragma unroll 1
    for (int st = 0; st < ODPER / OSLICE; st++) {
        if (st + 1 < ODPER / OSLICE) {
            stage((st + 1) & 1, d0 + (st + 1) * OSLICE);
            cp_wait<1>();
        } else {
            cp_wait<0>();
        }
        __syncthreads();

        const int b = st & 1;
#pragma unroll
        for (int s = 0; s < OSLICE; s++) {
            const int d = d0 + st * OSLICE + s;
            const float* P = sm[b] + s * (HALO * WW);

            float2 v = *(const float2*)&P[rB + x0];

            if (d != 0) {
                const float AL  = P[rA + xl];
                const float A0x = P[rA + x0];
                const float2 A1 = lastx ? make_float2(A0x, A0x)
                                        : *(const float2*)&P[rA + x0 + 2];
                const float DL  = P[rD + xl];
                const float D0x = P[rD + x0];
                const float2 D1 = lastx ? make_float2(D0x, D0x)
                                        : *(const float2*)&P[rD + x0 + 2];
                v.x = fmaf(w0.x, AL,  fmaf(w1.x, A1.x, fmaf(w2.x, DL,  fmaf(w3.x, D1.x, v.x))));
                v.y = fmaf(w0.y, A0x, fmaf(w1.y, A1.y, fmaf(w2.y, D0x, fmaf(w3.y, D1.y, v.y))));
            }

            v.x = cond.x != 0.f ? v.x : 0.f;
            v.y = cond.y != 0.f ? v.y : 0.f;

            *(float2*)&outB[(size_t)(st * OSLICE + s) * HW] = v;
        }
        __syncthreads();
    }
}

// ---------------------------------------------------------------------------
extern "C" void kernel_launch(void* const* d_in, const int* in_sizes, int n_in,
                              void* d_out, int out_size) {
    const float* cur  = (const float*)d_in[0];
    const float* prev = (const float*)d_in[1];
    const float* mem  = (const float*)d_in[2];
    float* out = (float*)d_out;

    k_partial<<<dim3(HH / TY, DCH, NB), dim3(32, TY)>>>(cur, prev);
    k_weights<<<dim3(HH / TY, NB), dim3(WW, TY)>>>();
    k_output<<<dim3(HH / TY, ODC, NB), dim3(32, TY)>>>(mem, out);
}

// round 8
// speedup vs baseline: 1.3493x; 1.0736x over previous
#include <cuda_runtime.h>

#define NB   4
#define DC   256
#define HH   64
#define WW   64
#define HW   4096
#define DCH  16       // chunks over D (pass 1)  -> 1024 blocks for occupancy
#define DPER 16       // D per chunk (pass 1)
#define NOFF 12
#define TY   4        // rows per tile
#define HALO 7        // TY + 3 halo rows (dy in -1..2)
#define DSLICE 4      // d-slices per pipeline stage (pass 1)
#define ODC  16       // d-chunks for k_output
#define ODPER 16      // d per k_output block
#define OSLICE 8      // d-slices per k_output stage

// offset order: 3x3 window row-major (idx 4 = (0,0)), then (-1,2),(2,-1),(2,2).
__device__ __constant__ int c_dy[NOFF] = {-1,-1,-1, 0,0,0, 1,1,1, -1, 2, 2};
__device__ __constant__ int c_dx[NOFF] = {-1, 0, 1,-1,0,1,-1,0,1,  2,-1, 2};

// scratch (no allocations allowed)
__device__ __align__(16) float g_part[(size_t)NB * DCH * 14 * HW];   // 14.7 MB
__device__ __align__(16) float g_red[(size_t)NB * 14 * HW];
__device__ __align__(16) float g_w0[NB * HW];
__device__ __align__(16) float g_w1[NB * HW];
__device__ __align__(16) float g_w2[NB * HW];
__device__ __align__(16) float g_w3[NB * HW];
__device__ __align__(16) float g_cond[NB * HW];

__device__ __forceinline__ int iclamp(int v, int lo, int hi) {
    return v < lo ? lo : (v > hi ? hi : v);
}

__device__ __forceinline__ void cp_async16(void* dst, const void* src) {
    unsigned int da = (unsigned int)__cvta_generic_to_shared(dst);
    asm volatile("cp.async.cg.shared.global [%0], [%1], 16;" :: "r"(da), "l"(src));
}
__device__ __forceinline__ void cp_commit() {
    asm volatile("cp.async.commit_group;");
}
template <int N>
__device__ __forceinline__ void cp_wait() {
    asm volatile("cp.async.wait_group %0;" :: "n"(N));
}

#define PREV_F (DSLICE * HALO * WW)     // 1792 floats
#define CUR_F  (DSLICE * TY * WW)       // 1024 floats
#define TOT_Q  ((PREV_F + CUR_F) / 4)   // 704 float4 per buffer

// ---------------------------------------------------------------------------
// Pass 1: cp.async double-buffered, 2 pixels/thread with vector LDS.
// grid (16 ytiles, 16 dchunks, 4 batch) = 1024 blocks, block (32,4) = 128 thr
// ---------------------------------------------------------------------------
__global__ __launch_bounds__(128) void k_partial(const float* __restrict__ cur,
                                                 const float* __restrict__ prev) {
    __shared__ float sp[2][PREV_F];
    __shared__ float sc[2][CUR_F];

    const int tx  = threadIdx.x;           // 0..31 -> pixels 2tx, 2tx+1
    const int ty  = threadIdx.y;           // 0..3
    const int y0  = blockIdx.x * TY;
    const int dch = blockIdx.y;
    const int n   = blockIdx.z;
    const int tid = ty * 32 + tx;
    const int x0  = tx * 2;

    const float* curB  = cur  + (size_t)n * DC * HW;
    const float* prevB = prev + (size_t)n * DC * HW;
    const int d0 = dch * DPER;

    auto stage = [&](int b, int dbase) {
#pragma unroll
        for (int j = 0; j < 6; j++) {
            const int i = tid + j * 128;
            if (i < PREV_F / 4) {
                const int s  = i / (HALO * 16);
                const int rm = i - s * (HALO * 16);
                const int r  = rm >> 4;
                const int c4 = rm & 15;
                const int gr = iclamp(y0 - 1 + r, 0, HH - 1);
                cp_async16(&sp[b][s * (HALO * WW) + r * WW + c4 * 4],
                           prevB + (size_t)(dbase + s) * HW + gr * WW + c4 * 4);
            } else if (i < TOT_Q) {
                const int k  = i - PREV_F / 4;
                const int s  = k >> 6;
                const int rm = k & 63;
                const int r  = rm >> 4;
                const int c4 = rm & 15;
                cp_async16(&sc[b][s * (TY * WW) + r * WW + c4 * 4],
                           curB + (size_t)(dbase + s) * HW + (y0 + r) * WW + c4 * 4);
            }
        }
        cp_commit();
    };

    const int rA = (ty    ) * WW;   // dy=-1
    const int rB = (ty + 1) * WW;   // dy= 0
    const int rC = (ty + 2) * WW;   // dy=+1
    const int rD = (ty + 3) * WW;   // dy=+2
    const int xl  = x0 == 0 ? 0 : x0 - 1;
    const int xr2 = x0 + 2 > WW - 1 ? WW - 1 : x0 + 2;
    const bool lastx = (tx == 31);

    float2 acc[14];
#pragma unroll
    for (int k = 0; k < 14; k++) acc[k] = make_float2(0.f, 0.f);

    stage(0, d0);

#pragma unroll 1
    for (int d4 = 0; d4 < DPER / DSLICE; d4++) {
        if (d4 + 1 < DPER / DSLICE) {
            stage((d4 + 1) & 1, d0 + (d4 + 1) * DSLICE);
            cp_wait<1>();
        } else {
            cp_wait<0>();
        }
        __syncthreads();

        const int b = d4 & 1;
#pragma unroll
        for (int s = 0; s < DSLICE; s++) {
            const float* P = sp[b] + s * (HALO * WW);
            const float2 c2 = *(const float2*)&sc[b][s * (TY * WW) + ty * WW + x0];

            const float2 A0 = *(const float2*)&P[rA + x0];
            const float2 B0 = *(const float2*)&P[rB + x0];
            const float2 C0 = *(const float2*)&P[rC + x0];
            const float2 D0 = *(const float2*)&P[rD + x0];
            const float  AL = P[rA + xl];
            const float  BL = P[rB + xl];
            const float  CL = P[rC + xl];
            const float  DL = P[rD + xl];
            const float2 A1 = lastx ? make_float2(A0.y, A0.y)
                                    : *(const float2*)&P[rA + x0 + 2];
            const float2 D1 = lastx ? make_float2(D0.y, D0.y)
                                    : *(const float2*)&P[rD + x0 + 2];
            const float  B2 = P[rB + xr2];
            const float  C2 = P[rC + xr2];

            const float c0 = c2.x, c1 = c2.y;
            acc[0].x  = fmaf(c0, AL,   acc[0].x);   acc[0].y  = fmaf(c1, A0.x, acc[0].y);
            acc[1].x  = fmaf(c0, A0.x, acc[1].x);   acc[1].y  = fmaf(c1, A0.y, acc[1].y);
            acc[2].x  = fmaf(c0, A0.y, acc[2].x);   acc[2].y  = fmaf(c1, A1.x, acc[2].y);
            acc[3].x  = fmaf(c0, BL,   acc[3].x);   acc[3].y  = fmaf(c1, B0.x, acc[3].y);
            acc[4].x  = fmaf(c0, B0.x, acc[4].x);   acc[4].y  = fmaf(c1, B0.y, acc[4].y);
            acc[5].x  = fmaf(c0, B0.y, acc[5].x);   acc[5].y  = fmaf(c1, B2,   acc[5].y);
            acc[6].x  = fmaf(c0, CL,   acc[6].x);   acc[6].y  = fmaf(c1, C0.x, acc[6].y);
            acc[7].x  = fmaf(c0, C0.x, acc[7].x);   acc[7].y  = fmaf(c1, C0.y, acc[7].y);
            acc[8].x  = fmaf(c0, C0.y, acc[8].x);   acc[8].y  = fmaf(c1, C2,   acc[8].y);
            acc[9].x  = fmaf(c0, A1.x, acc[9].x);   acc[9].y  = fmaf(c1, A1.y, acc[9].y);
            acc[10].x = fmaf(c0, DL,   acc[10].x);  acc[10].y = fmaf(c1, D0.x, acc[10].y);
            acc[11].x = fmaf(c0, D1.x, acc[11].x);  acc[11].y = fmaf(c1, D1.y, acc[11].y);
            acc[12].x = fmaf(c0, c0,   acc[12].x);  acc[12].y = fmaf(c1, c1,   acc[12].y);
            acc[13].x = fmaf(B0.x, B0.x, acc[13].x);
            acc[13].y = fmaf(B0.y, B0.y, acc[13].y);
        }
        __syncthreads();
    }

    const int pix = (y0 + ty) * WW + x0;
    float* o = g_part + (size_t)(n * DCH + dch) * 14 * HW + pix;
#pragma unroll
    for (int k = 0; k < 14; k++) *(float2*)&o[(size_t)k * HW] = acc[k];
}

// ---------------------------------------------------------------------------
// Pass 2a: reduce 16 D-chunks, float4-coalesced. 57344 threads.
// ---------------------------------------------------------------------------
__global__ __launch_bounds__(256) void k_reduce() {
    const int t    = blockIdx.x * blockDim.x + threadIdx.x;
    const int n    = t / (14 * 1024);
    const int r    = t - n * (14 * 1024);
    const int slot = r >> 10;
    const int p4   = (r & 1023) << 2;

    float4 a = make_float4(0.f, 0.f, 0.f, 0.f);
#pragma unroll
    for (int c = 0; c < DCH; c++) {
        const float4 v = *(const float4*)&g_part[(((size_t)(n * DCH + c)) * 14 + slot) * HW + p4];
        a.x += v.x; a.y += v.y; a.z += v.z; a.w += v.w;
    }
    *(float4*)&g_red[((size_t)n * 14 + slot) * HW + p4] = a;
}

// ---------------------------------------------------------------------------
// Pass 2b: cosine affinity -> cond + 4 agg weights (g_red L2-hot).
// grid (16, NB), block (64, 4)
// ---------------------------------------------------------------------------
__global__ __launch_bounds__(256) void k_weights() {
    __shared__ float s_pn[HALO * WW];

    const int x   = threadIdx.x;
    const int ty  = threadIdx.y;
    const int y0  = blockIdx.x * TY;
    const int n   = blockIdx.y;
    const int tid = ty * WW + x;

    const float* base = g_red + (size_t)n * 14 * HW;

    for (int i = tid; i < HALO * WW; i += 256) {
        const int r  = i >> 6;
        const int cc = i & (WW - 1);
        const int gr = iclamp(y0 - 1 + r, 0, HH - 1);
        s_pn[i] = sqrtf(base[(size_t)13 * HW + gr * WW + cc]) + 1e-8f;
    }
    __syncthreads();

    const int y   = y0 + ty;
    const int pix = y * WW + x;

    float acc[13];
#pragma unroll
    for (int k = 0; k < 13; k++) acc[k] = base[(size_t)k * HW + pix];

    const float invcn = 1.f / (sqrtf(acc[12]) + 1e-8f);

    float aff[NOFF];
#pragma unroll
    for (int k = 0; k < NOFF; k++) {
        const int py = y + c_dy[k];
        const int px = x + c_dx[k];
        const bool valid = (py >= 0) & (py < HH) & (px >= 0) & (px < WW);
        const int lr = ty + c_dy[k] + 1;
        const int lc = iclamp(px, 0, WW - 1);
        const float pn = s_pn[lr * WW + lc];
        float a = acc[k] * invcn / pn;
        a = fmaxf(a, 0.f);
        aff[k] = valid ? a : 0.f;
    }

    float mass = 0.f;
#pragma unroll
    for (int k = 0; k < 9; k++) mass += aff[k];

    const bool  cond = (mass > -10.f) && (mass < 10.f);
    const float inv  = 1.f / (mass > 0.f ? mass : 1.f);

    const int t = n * HW + pix;
    g_w0[t]   = aff[0]  > 0.f ? aff[0]  * inv : 0.f;  // (-1,-1)
    g_w1[t]   = aff[9]  > 0.f ? aff[9]  * inv : 0.f;  // (-1,+2)
    g_w2[t]   = aff[10] > 0.f ? aff[10] * inv : 0.f;  // (+2,-1)
    g_w3[t]   = aff[11] > 0.f ? aff[11] * inv : 0.f;  // (+2,+2)
    g_cond[t] = cond ? 1.f : 0.f;
}

// ---------------------------------------------------------------------------
// Pass 3: cp.async double-buffered, smem-tiled output. 2 stages of 8 d-slices.
// grid (16 ytiles, 16 dchunks, 4 batch) = 1024 blocks, block (32,4) = 128 thr
// ---------------------------------------------------------------------------
#define OMEM_F (OSLICE * HALO * WW)     // 3584 floats per buffer (14.3 KB)

__global__ __launch_bounds__(128) void k_output(const float* __restrict__ mem,
                                                float* __restrict__ out) {
    __shared__ float sm[2][OMEM_F];     // 28.7 KB

    const int tx  = threadIdx.x;           // 0..31 -> pixels 2tx, 2tx+1
    const int ty  = threadIdx.y;           // 0..3
    const int y0  = blockIdx.x * TY;
    const int dch = blockIdx.y;
    const int n   = blockIdx.z;
    const int tid = ty * 32 + tx;
    const int x0  = tx * 2;
    const int d0  = dch * ODPER;

    const float* memB = mem + (size_t)n * DC * HW;

    auto stage = [&](int b, int dbase) {
#pragma unroll
        for (int j = 0; j < 7; j++) {          // 896 float4 / 128 threads
            const int i = tid + j * 128;
            const int s  = i / (HALO * 16);
            const int rm = i - s * (HALO * 16);
            const int r  = rm >> 4;
            const int c4 = rm & 15;
            const int gr = iclamp(y0 - 1 + r, 0, HH - 1);
            cp_async16(&sm[b][s * (HALO * WW) + r * WW + c4 * 4],
                       memB + (size_t)(dbase + s) * HW + gr * WW + c4 * 4);
        }
        cp_commit();
    };

    const int y   = y0 + ty;
    const int np  = n * HW + y * WW + x0;
    const float2 cond = *(const float2*)&g_cond[np];
    const float2 w0   = *(const float2*)&g_w0[np];
    const float2 w1   = *(const float2*)&g_w1[np];
    const float2 w2   = *(const float2*)&g_w2[np];
    const float2 w3   = *(const float2*)&g_w3[np];

    const int rA = (ty    ) * WW;   // y-1
    const int rB = (ty + 1) * WW;   // y
    const int rD = (ty + 3) * WW;   // y+2
    const int xl = x0 == 0 ? 0 : x0 - 1;
    const bool lastx = (tx == 31);

    float* outB = out + ((size_t)n * DC + d0) * HW + y * WW + x0;

    stage(0, d0);

#pragma unroll 1
    for (int st = 0; st < ODPER / OSLICE; st++) {
        if (st + 1 < ODPER / OSLICE) {
            stage((st + 1) & 1, d0 + (st + 1) * OSLICE);
            cp_wait<1>();
        } else {
            cp_wait<0>();
        }
        __syncthreads();

        const int b = st & 1;
#pragma unroll
        for (int s = 0; s < OSLICE; s++) {
            const int d = d0 + st * OSLICE + s;
            const float* P = sm[b] + s * (HALO * WW);

            float2 v = *(const float2*)&P[rB + x0];

            if (d != 0) {
                const float AL  = P[rA + xl];
                const float A0x = P[rA + x0];
                const float2 A1 = lastx ? make_float2(A0x, A0x)
                                        : *(const float2*)&P[rA + x0 + 2];
                const float DL  = P[rD + xl];
                const float D0x = P[rD + x0];
                const float2 D1 = lastx ? make_float2(D0x, D0x)
                                        : *(const float2*)&P[rD + x0 + 2];
                v.x = fmaf(w0.x, AL,  fmaf(w1.x, A1.x, fmaf(w2.x, DL,  fmaf(w3.x, D1.x, v.x))));
                v.y = fmaf(w0.y, A0x, fmaf(w1.y, A1.y, fmaf(w2.y, D0x, fmaf(w3.y, D1.y, v.y))));
            }

            v.x = cond.x != 0.f ? v.x : 0.f;
            v.y = cond.y != 0.f ? v.y : 0.f;

            *(float2*)&outB[(size_t)(st * OSLICE + s) * HW] = v;
        }
        __syncthreads();
    }
}

// ---------------------------------------------------------------------------
extern "C" void kernel_launch(void* const* d_in, const int* in_sizes, int n_in,
                              void* d_out, int out_size) {
    const float* cur  = (const float*)d_in[0];
    const float* prev = (const float*)d_in[1];
    const float* mem  = (const float*)d_in[2];
    float* out = (float*)d_out;

    k_partial<<<dim3(HH / TY, DCH, NB), dim3(32, TY)>>>(cur, prev);
    k_reduce<<<(NB * 14 * HW / 4) / 256, 256>>>();
    k_weights<<<dim3(HH / TY, NB), dim3(WW, TY)>>>();
    k_output<<<dim3(HH / TY, ODC, NB), dim3(32, TY)>>>(mem, out);
}

// round 9
// speedup vs baseline: 1.3525x; 1.0023x over previous
#include <cuda_runtime.h>

#define NB   4
#define DC   256
#define HH   64
#define WW   64
#define HW   4096
#define DCH  16       // chunks over D (pass 1)  -> 1024 blocks for occupancy
#define DPER 16       // D per chunk (pass 1)
#define NOFF 12
#define TY   4        // rows per tile
#define HALO 7        // TY + 3 halo rows (dy in -1..2)
#define DSLICE 4      // d-slices per pipeline stage (pass 1)
#define ODC  32       // d-chunks for k_output -> 2048 blocks
#define ODPER 8       // d per k_output block
#define OSLICE 4      // d-slices per k_output stage

// offset order: 3x3 window row-major (idx 4 = (0,0)), then (-1,2),(2,-1),(2,2).
__device__ __constant__ int c_dy[NOFF] = {-1,-1,-1, 0,0,0, 1,1,1, -1, 2, 2};
__device__ __constant__ int c_dx[NOFF] = {-1, 0, 1,-1,0,1,-1,0,1,  2,-1, 2};

// scratch (no allocations allowed)
__device__ __align__(16) float g_part[(size_t)NB * DCH * 14 * HW];   // 14.7 MB
__device__ __align__(16) float g_red[(size_t)NB * 14 * HW];
__device__ __align__(16) float g_w0[NB * HW];
__device__ __align__(16) float g_w1[NB * HW];
__device__ __align__(16) float g_w2[NB * HW];
__device__ __align__(16) float g_w3[NB * HW];
__device__ __align__(16) float g_cond[NB * HW];

__device__ __forceinline__ int iclamp(int v, int lo, int hi) {
    return v < lo ? lo : (v > hi ? hi : v);
}

__device__ __forceinline__ void cp_async16(void* dst, const void* src) {
    unsigned int da = (unsigned int)__cvta_generic_to_shared(dst);
    asm volatile("cp.async.cg.shared.global [%0], [%1], 16;" :: "r"(da), "l"(src));
}
__device__ __forceinline__ void cp_commit() {
    asm volatile("cp.async.commit_group;");
}
template <int N>
__device__ __forceinline__ void cp_wait() {
    asm volatile("cp.async.wait_group %0;" :: "n"(N));
}
__device__ __forceinline__ void prefetch_l2(const void* p) {
    asm volatile("prefetch.global.L2 [%0];" :: "l"(p));
}

#define PREV_F (DSLICE * HALO * WW)     // 1792 floats
#define CUR_F  (DSLICE * TY * WW)       // 1024 floats
#define TOT_Q  ((PREV_F + CUR_F) / 4)   // 704 float4 per buffer

// ---------------------------------------------------------------------------
// Pass 1: cp.async double-buffered, 2 pixels/thread with vector LDS.
// grid (16 ytiles, 16 dchunks, 4 batch) = 1024 blocks, block (32,4) = 128 thr
// Also L2-prefetches the matching mem tile for k_output.
// ---------------------------------------------------------------------------
__global__ __launch_bounds__(128) void k_partial(const float* __restrict__ cur,
                                                 const float* __restrict__ prev,
                                                 const float* __restrict__ mem) {
    __shared__ float sp[2][PREV_F];
    __shared__ float sc[2][CUR_F];

    const int tx  = threadIdx.x;           // 0..31 -> pixels 2tx, 2tx+1
    const int ty  = threadIdx.y;           // 0..3
    const int y0  = blockIdx.x * TY;
    const int dch = blockIdx.y;
    const int n   = blockIdx.z;
    const int tid = ty * 32 + tx;
    const int x0  = tx * 2;

    const float* curB  = cur  + (size_t)n * DC * HW;
    const float* prevB = prev + (size_t)n * DC * HW;
    const int d0 = dch * DPER;

    auto stage = [&](int b, int dbase) {
#pragma unroll
        for (int j = 0; j < 6; j++) {
            const int i = tid + j * 128;
            if (i < PREV_F / 4) {
                const int s  = i / (HALO * 16);
                const int rm = i - s * (HALO * 16);
                const int r  = rm >> 4;
                const int c4 = rm & 15;
                const int gr = iclamp(y0 - 1 + r, 0, HH - 1);
                cp_async16(&sp[b][s * (HALO * WW) + r * WW + c4 * 4],
                           prevB + (size_t)(dbase + s) * HW + gr * WW + c4 * 4);
            } else if (i < TOT_Q) {
                const int k  = i - PREV_F / 4;
                const int s  = k >> 6;
                const int rm = k & 63;
                const int r  = rm >> 4;
                const int c4 = rm & 15;
                cp_async16(&sc[b][s * (TY * WW) + r * WW + c4 * 4],
                           curB + (size_t)(dbase + s) * HW + (y0 + r) * WW + c4 * 4);
            }
        }
        cp_commit();
    };

    stage(0, d0);

    // L2-prefetch this block's mem tile (16 d-planes x 4 rows = 128 lines,
    // one 128B line per thread) so k_output later hits L2 instead of DRAM.
    {
        const float* memB = mem + (size_t)n * DC * HW;
        const int dd   = tid >> 3;          // 0..15
        const int r    = (tid >> 1) & 3;    // 0..3
        const int half = tid & 1;           // 0..1
        prefetch_l2(memB + (size_t)(d0 + dd) * HW + (y0 + r) * WW + half * 32);
    }

    const int rA = (ty    ) * WW;   // dy=-1
    const int rB = (ty + 1) * WW;   // dy= 0
    const int rC = (ty + 2) * WW;   // dy=+1
    const int rD = (ty + 3) * WW;   // dy=+2
    const int xl  = x0 == 0 ? 0 : x0 - 1;
    const int xr2 = x0 + 2 > WW - 1 ? WW - 1 : x0 + 2;
    const bool lastx = (tx == 31);

    float2 acc[14];
#pragma unroll
    for (int k = 0; k < 14; k++) acc[k] = make_float2(0.f, 0.f);

#pragma unroll 1
    for (int d4 = 0; d4 < DPER / DSLICE; d4++) {
        if (d4 + 1 < DPER / DSLICE) {
            stage((d4 + 1) & 1, d0 + (d4 + 1) * DSLICE);
            cp_wait<1>();
        } else {
            cp_wait<0>();
        }
        __syncthreads();

        const int b = d4 & 1;
#pragma unroll
        for (int s = 0; s < DSLICE; s++) {
            const float* P = sp[b] + s * (HALO * WW);
            const float2 c2 = *(const float2*)&sc[b][s * (TY * WW) + ty * WW + x0];

            const float2 A0 = *(const float2*)&P[rA + x0];
            const float2 B0 = *(const float2*)&P[rB + x0];
            const float2 C0 = *(const float2*)&P[rC + x0];
            const float2 D0 = *(const float2*)&P[rD + x0];
            const float  AL = P[rA + xl];
            const float  BL = P[rB + xl];
            const float  CL = P[rC + xl];
            const float  DL = P[rD + xl];
            const float2 A1 = lastx ? make_float2(A0.y, A0.y)
                                    : *(const float2*)&P[rA + x0 + 2];
            const float2 D1 = lastx ? make_float2(D0.y, D0.y)
                                    : *(const float2*)&P[rD + x0 + 2];
            const float  B2 = P[rB + xr2];
            const float  C2 = P[rC + xr2];

            const float c0 = c2.x, c1 = c2.y;
            acc[0].x  = fmaf(c0, AL,   acc[0].x);   acc[0].y  = fmaf(c1, A0.x, acc[0].y);
            acc[1].x  = fmaf(c0, A0.x, acc[1].x);   acc[1].y  = fmaf(c1, A0.y, acc[1].y);
            acc[2].x  = fmaf(c0, A0.y, acc[2].x);   acc[2].y  = fmaf(c1, A1.x, acc[2].y);
            acc[3].x  = fmaf(c0, BL,   acc[3].x);   acc[3].y  = fmaf(c1, B0.x, acc[3].y);
            acc[4].x  = fmaf(c0, B0.x, acc[4].x);   acc[4].y  = fmaf(c1, B0.y, acc[4].y);
            acc[5].x  = fmaf(c0, B0.y, acc[5].x);   acc[5].y  = fmaf(c1, B2,   acc[5].y);
            acc[6].x  = fmaf(c0, CL,   acc[6].x);   acc[6].y  = fmaf(c1, C0.x, acc[6].y);
            acc[7].x  = fmaf(c0, C0.x, acc[7].x);   acc[7].y  = fmaf(c1, C0.y, acc[7].y);
            acc[8].x  = fmaf(c0, C0.y, acc[8].x);   acc[8].y  = fmaf(c1, C2,   acc[8].y);
            acc[9].x  = fmaf(c0, A1.x, acc[9].x);   acc[9].y  = fmaf(c1, A1.y, acc[9].y);
            acc[10].x = fmaf(c0, DL,   acc[10].x);  acc[10].y = fmaf(c1, D0.x, acc[10].y);
            acc[11].x = fmaf(c0, D1.x, acc[11].x);  acc[11].y = fmaf(c1, D1.y, acc[11].y);
            acc[12].x = fmaf(c0, c0,   acc[12].x);  acc[12].y = fmaf(c1, c1,   acc[12].y);
            acc[13].x = fmaf(B0.x, B0.x, acc[13].x);
            acc[13].y = fmaf(B0.y, B0.y, acc[13].y);
        }
        __syncthreads();
    }

    const int pix = (y0 + ty) * WW + x0;
    float* o = g_part + (size_t)(n * DCH + dch) * 14 * HW + pix;
#pragma unroll
    for (int k = 0; k < 14; k++) *(float2*)&o[(size_t)k * HW] = acc[k];
}

// ---------------------------------------------------------------------------
// Pass 2a: reduce 16 D-chunks, float4-coalesced. 57344 threads.
// ---------------------------------------------------------------------------
__global__ __launch_bounds__(256) void k_reduce() {
    const int t    = blockIdx.x * blockDim.x + threadIdx.x;
    const int n    = t / (14 * 1024);
    const int r    = t - n * (14 * 1024);
    const int slot = r >> 10;
    const int p4   = (r & 1023) << 2;

    float4 a = make_float4(0.f, 0.f, 0.f, 0.f);
#pragma unroll
    for (int c = 0; c < DCH; c++) {
        const float4 v = *(const float4*)&g_part[(((size_t)(n * DCH + c)) * 14 + slot) * HW + p4];
        a.x += v.x; a.y += v.y; a.z += v.z; a.w += v.w;
    }
    *(float4*)&g_red[((size_t)n * 14 + slot) * HW + p4] = a;
}

// ---------------------------------------------------------------------------
// Pass 2b: cosine affinity -> cond + 4 agg weights (g_red L2-hot).
// grid (16, NB), block (64, 4)
// ---------------------------------------------------------------------------
__global__ __launch_bounds__(256) void k_weights() {
    __shared__ float s_pn[HALO * WW];

    const int x   = threadIdx.x;
    const int ty  = threadIdx.y;
    const int y0  = blockIdx.x * TY;
    const int n   = blockIdx.y;
    const int tid = ty * WW + x;

    const float* base = g_red + (size_t)n * 14 * HW;

    for (int i = tid; i < HALO * WW; i += 256) {
        const int r  = i >> 6;
        const int cc = i & (WW - 1);
        const int gr = iclamp(y0 - 1 + r, 0, HH - 1);
        s_pn[i] = sqrtf(base[(size_t)13 * HW + gr * WW + cc]) + 1e-8f;
    }
    __syncthreads();

    const int y   = y0 + ty;
    const int pix = y * WW + x;

    float acc[13];
#pragma unroll
    for (int k = 0; k < 13; k++) acc[k] = base[(size_t)k * HW + pix];

    const float invcn = 1.f / (sqrtf(acc[12]) + 1e-8f);

    float aff[NOFF];
#pragma unroll
    for (int k = 0; k < NOFF; k++) {
        const int py = y + c_dy[k];
        const int px = x + c_dx[k];
        const bool valid = (py >= 0) & (py < HH) & (px >= 0) & (px < WW);
        const int lr = ty + c_dy[k] + 1;
        const int lc = iclamp(px, 0, WW - 1);
        const float pn = s_pn[lr * WW + lc];
        float a = acc[k] * invcn / pn;
        a = fmaxf(a, 0.f);
        aff[k] = valid ? a : 0.f;
    }

    float mass = 0.f;
#pragma unroll
    for (int k = 0; k < 9; k++) mass += aff[k];

    const bool  cond = (mass > -10.f) && (mass < 10.f);
    const float inv  = 1.f / (mass > 0.f ? mass : 1.f);

    const int t = n * HW + pix;
    g_w0[t]   = aff[0]  > 0.f ? aff[0]  * inv : 0.f;  // (-1,-1)
    g_w1[t]   = aff[9]  > 0.f ? aff[9]  * inv : 0.f;  // (-1,+2)
    g_w2[t]   = aff[10] > 0.f ? aff[10] * inv : 0.f;  // (+2,-1)
    g_w3[t]   = aff[11] > 0.f ? aff[11] * inv : 0.f;  // (+2,+2)
    g_cond[t] = cond ? 1.f : 0.f;
}

// ---------------------------------------------------------------------------
// Pass 3: cp.async double-buffered, smem-tiled output. mem is L2-prefetched.
// grid (16 ytiles, 32 dchunks, 4 batch) = 2048 blocks, block (32,4) = 128 thr
// ---------------------------------------------------------------------------
#define OMEM_F (OSLICE * HALO * WW)     // 1792 floats per buffer (7.2 KB)

__global__ __launch_bounds__(128) void k_output(const float* __restrict__ mem,
                                                float* __restrict__ out) {
    __shared__ float sm[2][OMEM_F];     // 14.3 KB

    const int tx  = threadIdx.x;           // 0..31 -> pixels 2tx, 2tx+1
    const int ty  = threadIdx.y;           // 0..3
    const int y0  = blockIdx.x * TY;
    const int dch = blockIdx.y;
    const int n   = blockIdx.z;
    const int tid = ty * 32 + tx;
    const int x0  = tx * 2;
    const int d0  = dch * ODPER;

    const float* memB = mem + (size_t)n * DC * HW;

    auto stage = [&](int b, int dbase) {
#pragma unroll
        for (int j = 0; j < 4; j++) {          // 448 float4 / 128 threads
            const int i = tid + j * 128;
            if (i < OMEM_F / 4) {
                const int s  = i / (HALO * 16);
                const int rm = i - s * (HALO * 16);
                const int r  = rm >> 4;
                const int c4 = rm & 15;
                const int gr = iclamp(y0 - 1 + r, 0, HH - 1);
                cp_async16(&sm[b][s * (HALO * WW) + r * WW + c4 * 4],
                           memB + (size_t)(dbase + s) * HW + gr * WW + c4 * 4);
            }
        }
        cp_commit();
    };

    const int y   = y0 + ty;
    const int np  = n * HW + y * WW + x0;
    const float2 cond = *(const float2*)&g_cond[np];
    const float2 w0   = *(const float2*)&g_w0[np];
    const float2 w1   = *(const float2*)&g_w1[np];
    const float2 w2   = *(const float2*)&g_w2[np];
    const float2 w3   = *(const float2*)&g_w3[np];

    const int rA = (ty    ) * WW;   // y-1
    const int rB = (ty + 1) * WW;   // y
    const int rD = (ty + 3) * WW;   // y+2
    const int xl = x0 == 0 ? 0 : x0 - 1;
    const bool lastx = (tx == 31);

    float* outB = out + ((size_t)n * DC + d0) * HW + y * WW + x0;

    stage(0, d0);

#pragma unroll 1
    for (int st = 0; st < ODPER / OSLICE; st++) {
        if (st + 1 < ODPER / OSLICE) {
            stage((st + 1) & 1, d0 + (st + 1) * OSLICE);
            cp_wait<1>();
        } else {
            cp_wait<0>();
        }
        __syncthreads();

        const int b = st & 1;
#pragma unroll
        for (int s = 0; s < OSLICE; s++) {
            const int d = d0 + st * OSLICE + s;
            const float* P = sm[b] + s * (HALO * WW);

            float2 v = *(const float2*)&P[rB + x0];

            if (d != 0) {
                const float AL  = P[rA + xl];
                const float A0x = P[rA + x0];
                const float2 A1 = lastx ? make_float2(A0x, A0x)
                                        : *(const float2*)&P[rA + x0 + 2];
                const float DL  = P[rD + xl];
                const float D0x = P[rD + x0];
                const float2 D1 = lastx ? make_float2(D0x, D0x)
                                        : *(const float2*)&P[rD + x0 + 2];
                v.x = fmaf(w0.x, AL,  fmaf(w1.x, A1.x, fmaf(w2.x, DL,  fmaf(w3.x, D1.x, v.x))));
                v.y = fmaf(w0.y, A0x, fmaf(w1.y, A1.y, fmaf(w2.y, D0x, fmaf(w3.y, D1.y, v.y))));
            }

            v.x = cond.x != 0.f ? v.x : 0.f;
            v.y = cond.y != 0.f ? v.y : 0.f;

            *(float2*)&outB[(size_t)(st * OSLICE + s) * HW] = v;
        }
        __syncthreads();
    }
}

// ---------------------------------------------------------------------------
extern "C" void kernel_launch(void* const* d_in, const int* in_sizes, int n_in,
                              void* d_out, int out_size) {
    const float* cur  = (const float*)d_in[0];
    const float* prev = (const float*)d_in[1];
    const float* mem  = (const float*)d_in[2];
    float* out = (float*)d_out;

    k_partial<<<dim3(HH / TY, DCH, NB), dim3(32, TY)>>>(cur, prev, mem);
    k_reduce<<<(NB * 14 * HW / 4) / 256, 256>>>();
    k_weights<<<dim3(HH / TY, NB), dim3(WW, TY)>>>();
    k_output<<<dim3(HH / TY, ODC, NB), dim3(32, TY)>>>(mem, out);
}

// round 10
// speedup vs baseline: 1.3636x; 1.0083x over previous
#include <cuda_runtime.h>

#define NB   4
#define DC   256
#define HH   64
#define WW   64
#define HW   4096
#define DCH  16       // chunks over D (pass 1)
#define DPER 16       // D per chunk (pass 1)
#define NOFF 12
#define TY   4        // rows per tile (pass 1 / pass 2b)
#define HALO 7        // TY + 3 halo rows
#define DSLICE 4      // d-slices per pipeline stage (pass 1)
#define ODC  32       // d-chunks for k_output
#define ODPER 8       // d per k_output block
#define OSLICE 4      // d-slices per k_output stage
#define OTY  8        // rows per k_output tile
#define OHALO 11      // OTY + 3

// offset order: 3x3 window row-major (idx 4 = (0,0)), then (-1,2),(2,-1),(2,2).
__device__ __constant__ int c_dy[NOFF] = {-1,-1,-1, 0,0,0, 1,1,1, -1, 2, 2};
__device__ __constant__ int c_dx[NOFF] = {-1, 0, 1,-1,0,1,-1,0,1,  2,-1, 2};

// scratch (no allocations allowed)
__device__ __align__(16) float g_part[(size_t)NB * DCH * 14 * HW];   // 14.7 MB
__device__ __align__(16) float g_red[(size_t)NB * 14 * HW];
__device__ __align__(16) float g_w0[NB * HW];
__device__ __align__(16) float g_w1[NB * HW];
__device__ __align__(16) float g_w2[NB * HW];
__device__ __align__(16) float g_w3[NB * HW];
__device__ __align__(16) float g_cond[NB * HW];

__device__ __forceinline__ int iclamp(int v, int lo, int hi) {
    return v < lo ? lo : (v > hi ? hi : v);
}

__device__ __forceinline__ void cp_async16(void* dst, const void* src) {
    unsigned int da = (unsigned int)__cvta_generic_to_shared(dst);
    asm volatile("cp.async.cg.shared.global [%0], [%1], 16;" :: "r"(da), "l"(src));
}
__device__ __forceinline__ void cp_commit() {
    asm volatile("cp.async.commit_group;");
}
template <int N>
__device__ __forceinline__ void cp_wait() {
    asm volatile("cp.async.wait_group %0;" :: "n"(N));
}
__device__ __forceinline__ void prefetch_l2(const void* p) {
    asm volatile("prefetch.global.L2 [%0];" :: "l"(p));
}

#define PREV_F (DSLICE * HALO * WW)     // 1792 floats
#define CUR_F  (DSLICE * TY * WW)       // 1024 floats
#define TOT_Q  ((PREV_F + CUR_F) / 4)   // 704 float4 per buffer

// ---------------------------------------------------------------------------
// Pass 1: cp.async double-buffered, 2 pixels/thread with vector LDS.
// grid (16 ytiles, 16 dchunks, 4 batch) = 1024 blocks, block (32,4) = 128 thr
// ---------------------------------------------------------------------------
__global__ __launch_bounds__(128) void k_partial(const float* __restrict__ cur,
                                                 const float* __restrict__ prev,
                                                 const float* __restrict__ mem) {
    __shared__ float sp[2][PREV_F];
    __shared__ float sc[2][CUR_F];

    const int tx  = threadIdx.x;           // 0..31 -> pixels 2tx, 2tx+1
    const int ty  = threadIdx.y;           // 0..3
    const int y0  = blockIdx.x * TY;
    const int dch = blockIdx.y;
    const int n   = blockIdx.z;
    const int tid = ty * 32 + tx;
    const int x0  = tx * 2;

    const float* curB  = cur  + (size_t)n * DC * HW;
    const float* prevB = prev + (size_t)n * DC * HW;
    const int d0 = dch * DPER;

    auto stage = [&](int b, int dbase) {
#pragma unroll
        for (int j = 0; j < 6; j++) {
            const int i = tid + j * 128;
            if (i < PREV_F / 4) {
                const int s  = i / (HALO * 16);
                const int rm = i - s * (HALO * 16);
                const int r  = rm >> 4;
                const int c4 = rm & 15;
                const int gr = iclamp(y0 - 1 + r, 0, HH - 1);
                cp_async16(&sp[b][s * (HALO * WW) + r * WW + c4 * 4],
                           prevB + (size_t)(dbase + s) * HW + gr * WW + c4 * 4);
            } else if (i < TOT_Q) {
                const int k  = i - PREV_F / 4;
                const int s  = k >> 6;
                const int rm = k & 63;
                const int r  = rm >> 4;
                const int c4 = rm & 15;
                cp_async16(&sc[b][s * (TY * WW) + r * WW + c4 * 4],
                           curB + (size_t)(dbase + s) * HW + (y0 + r) * WW + c4 * 4);
            }
        }
        cp_commit();
    };

    stage(0, d0);

    // L2-prefetch mem so k_output hits L2 (one 128B line per thread)
    {
        const float* memB = mem + (size_t)n * DC * HW;
        const int dd   = tid >> 3;
        const int r    = (tid >> 1) & 3;
        const int half = tid & 1;
        prefetch_l2(memB + (size_t)(d0 + dd) * HW + (y0 + r) * WW + half * 32);
    }

    const int rA = (ty    ) * WW;
    const int rB = (ty + 1) * WW;
    const int rC = (ty + 2) * WW;
    const int rD = (ty + 3) * WW;
    const int xl  = x0 == 0 ? 0 : x0 - 1;
    const int xr2 = x0 + 2 > WW - 1 ? WW - 1 : x0 + 2;
    const bool lastx = (tx == 31);

    float2 acc[14];
#pragma unroll
    for (int k = 0; k < 14; k++) acc[k] = make_float2(0.f, 0.f);

#pragma unroll 1
    for (int d4 = 0; d4 < DPER / DSLICE; d4++) {
        if (d4 + 1 < DPER / DSLICE) {
            stage((d4 + 1) & 1, d0 + (d4 + 1) * DSLICE);
            cp_wait<1>();
        } else {
            cp_wait<0>();
        }
        __syncthreads();

        const int b = d4 & 1;
#pragma unroll
        for (int s = 0; s < DSLICE; s++) {
            const float* P = sp[b] + s * (HALO * WW);
            const float2 c2 = *(const float2*)&sc[b][s * (TY * WW) + ty * WW + x0];

            const float2 A0 = *(const float2*)&P[rA + x0];
            const float2 B0 = *(const float2*)&P[rB + x0];
            const float2 C0 = *(const float2*)&P[rC + x0];
            const float2 D0 = *(const float2*)&P[rD + x0];
            const float  AL = P[rA + xl];
            const float  BL = P[rB + xl];
            const float  CL = P[rC + xl];
            const float  DL = P[rD + xl];
            const float2 A1 = lastx ? make_float2(A0.y, A0.y)
                                    : *(const float2*)&P[rA + x0 + 2];
            const float2 D1 = lastx ? make_float2(D0.y, D0.y)
                                    : *(const float2*)&P[rD + x0 + 2];
            const float  B2 = P[rB + xr2];
            const float  C2 = P[rC + xr2];

            const float c0 = c2.x, c1 = c2.y;
            acc[0].x  = fmaf(c0, AL,   acc[0].x);   acc[0].y  = fmaf(c1, A0.x, acc[0].y);
            acc[1].x  = fmaf(c0, A0.x, acc[1].x);   acc[1].y  = fmaf(c1, A0.y, acc[1].y);
            acc[2].x  = fmaf(c0, A0.y, acc[2].x);   acc[2].y  = fmaf(c1, A1.x, acc[2].y);
            acc[3].x  = fmaf(c0, BL,   acc[3].x);   acc[3].y  = fmaf(c1, B0.x, acc[3].y);
            acc[4].x  = fmaf(c0, B0.x, acc[4].x);   acc[4].y  = fmaf(c1, B0.y, acc[4].y);
            acc[5].x  = fmaf(c0, B0.y, acc[5].x);   acc[5].y  = fmaf(c1, B2,   acc[5].y);
            acc[6].x  = fmaf(c0, CL,   acc[6].x);   acc[6].y  = fmaf(c1, C0.x, acc[6].y);
            acc[7].x  = fmaf(c0, C0.x, acc[7].x);   acc[7].y  = fmaf(c1, C0.y, acc[7].y);
            acc[8].x  = fmaf(c0, C0.y, acc[8].x);   acc[8].y  = fmaf(c1, C2,   acc[8].y);
            acc[9].x  = fmaf(c0, A1.x, acc[9].x);   acc[9].y  = fmaf(c1, A1.y, acc[9].y);
            acc[10].x = fmaf(c0, DL,   acc[10].x);  acc[10].y = fmaf(c1, D0.x, acc[10].y);
            acc[11].x = fmaf(c0, D1.x, acc[11].x);  acc[11].y = fmaf(c1, D1.y, acc[11].y);
            acc[12].x = fmaf(c0, c0,   acc[12].x);  acc[12].y = fmaf(c1, c1,   acc[12].y);
            acc[13].x = fmaf(B0.x, B0.x, acc[13].x);
            acc[13].y = fmaf(B0.y, B0.y, acc[13].y);
        }
        __syncthreads();
    }

    const int pix = (y0 + ty) * WW + x0;
    float* o = g_part + (size_t)(n * DCH + dch) * 14 * HW + pix;
#pragma unroll
    for (int k = 0; k < 14; k++) *(float2*)&o[(size_t)k * HW] = acc[k];
}

// ---------------------------------------------------------------------------
// Pass 2a: reduce 16 D-chunks, float4-coalesced. 57344 threads.
// ---------------------------------------------------------------------------
__global__ __launch_bounds__(256) void k_reduce() {
    const int t    = blockIdx.x * blockDim.x + threadIdx.x;
    const int n    = t / (14 * 1024);
    const int r    = t - n * (14 * 1024);
    const int slot = r >> 10;
    const int p4   = (r & 1023) << 2;

    float4 a = make_float4(0.f, 0.f, 0.f, 0.f);
#pragma unroll
    for (int c = 0; c < DCH; c++) {
        const float4 v = *(const float4*)&g_part[(((size_t)(n * DCH + c)) * 14 + slot) * HW + p4];
        a.x += v.x; a.y += v.y; a.z += v.z; a.w += v.w;
    }
    *(float4*)&g_red[((size_t)n * 14 + slot) * HW + p4] = a;
}

// ---------------------------------------------------------------------------
// Pass 2b: cosine affinity -> cond + 4 agg weights (g_red L2-hot).
// ---------------------------------------------------------------------------
__global__ __launch_bounds__(256) void k_weights() {
    __shared__ float s_pn[HALO * WW];

    const int x   = threadIdx.x;
    const int ty  = threadIdx.y;
    const int y0  = blockIdx.x * TY;
    const int n   = blockIdx.y;
    const int tid = ty * WW + x;

    const float* base = g_red + (size_t)n * 14 * HW;

    for (int i = tid; i < HALO * WW; i += 256) {
        const int r  = i >> 6;
        const int cc = i & (WW - 1);
        const int gr = iclamp(y0 - 1 + r, 0, HH - 1);
        s_pn[i] = sqrtf(base[(size_t)13 * HW + gr * WW + cc]) + 1e-8f;
    }
    __syncthreads();

    const int y   = y0 + ty;
    const int pix = y * WW + x;

    float acc[13];
#pragma unroll
    for (int k = 0; k < 13; k++) acc[k] = base[(size_t)k * HW + pix];

    const float invcn = 1.f / (sqrtf(acc[12]) + 1e-8f);

    float aff[NOFF];
#pragma unroll
    for (int k = 0; k < NOFF; k++) {
        const int py = y + c_dy[k];
        const int px = x + c_dx[k];
        const bool valid = (py >= 0) & (py < HH) & (px >= 0) & (px < WW);
        const int lr = ty + c_dy[k] + 1;
        const int lc = iclamp(px, 0, WW - 1);
        const float pn = s_pn[lr * WW + lc];
        float a = acc[k] * invcn / pn;
        a = fmaxf(a, 0.f);
        aff[k] = valid ? a : 0.f;
    }

    float mass = 0.f;
#pragma unroll
    for (int k = 0; k < 9; k++) mass += aff[k];

    const bool  cond = (mass > -10.f) && (mass < 10.f);
    const float inv  = 1.f / (mass > 0.f ? mass : 1.f);

    const int t = n * HW + pix;
    g_w0[t]   = aff[0]  > 0.f ? aff[0]  * inv : 0.f;  // (-1,-1)
    g_w1[t]   = aff[9]  > 0.f ? aff[9]  * inv : 0.f;  // (-1,+2)
    g_w2[t]   = aff[10] > 0.f ? aff[10] * inv : 0.f;  // (+2,-1)
    g_w3[t]   = aff[11] > 0.f ? aff[11] * inv : 0.f;  // (+2,+2)
    g_cond[t] = cond ? 1.f : 0.f;
}

// ---------------------------------------------------------------------------
// Pass 3: 4 pixels/thread, float4 LDS + STG.128, cp.async double-buffered.
// grid (8 ytiles, 32 dchunks, 4 batch) = 1024 blocks, block (16,8) = 128 thr
// ---------------------------------------------------------------------------
#define OMEM_F (OSLICE * OHALO * WW)     // 2816 floats per buffer (11.3 KB)

__global__ __launch_bounds__(128) void k_output(const float* __restrict__ mem,
                                                float* __restrict__ out) {
    __shared__ float sm[2][OMEM_F];      // 22.5 KB

    const int tx  = threadIdx.x;            // 0..15 -> pixels 4tx..4tx+3
    const int ty  = threadIdx.y;            // 0..7
    const int y0  = blockIdx.x * OTY;
    const int dch = blockIdx.y;
    const int n   = blockIdx.z;
    const int tid = ty * 16 + tx;           // 0..127
    const int x0  = tx * 4;
    const int d0  = dch * ODPER;

    const float* memB = mem + (size_t)n * DC * HW;

    auto stage = [&](int b, int dbase) {
#pragma unroll
        for (int j = 0; j < 6; j++) {          // 704 float4 / 128 threads
            const int i = tid + j * 128;
            if (i < OMEM_F / 4) {
                const int s  = i / (OHALO * 16);
                const int rm = i - s * (OHALO * 16);
                const int r  = rm >> 4;
                const int c4 = rm & 15;
                const int gr = iclamp(y0 - 1 + r, 0, HH - 1);
                cp_async16(&sm[b][s * (OHALO * WW) + r * WW + c4 * 4],
                           memB + (size_t)(dbase + s) * HW + gr * WW + c4 * 4);
            }
        }
        cp_commit();
    };

    // per-thread weights for its 4 pixels (once per block)
    const int y   = y0 + ty;
    const int np  = n * HW + y * WW + x0;
    const float4 cond = *(const float4*)&g_cond[np];
    const float4 w0   = *(const float4*)&g_w0[np];
    const float4 w1   = *(const float4*)&g_w1[np];
    const float4 w2   = *(const float4*)&g_w2[np];
    const float4 w3   = *(const float4*)&g_w3[np];

    const int rA = (ty    ) * WW;   // y-1
    const int rB = (ty + 1) * WW;   // y
    const int rD = (ty + 3) * WW;   // y+2
    const bool firstx = (tx == 0);
    const bool lastx  = (tx == 15);

    float* outB = out + ((size_t)n * DC + d0) * HW + y * WW + x0;

    stage(0, d0);

#pragma unroll 1
    for (int st = 0; st < ODPER / OSLICE; st++) {
        if (st + 1 < ODPER / OSLICE) {
            stage((st + 1) & 1, d0 + (st + 1) * OSLICE);
            cp_wait<1>();
        } else {
            cp_wait<0>();
        }
        __syncthreads();

        const int b = st & 1;
#pragma unroll
        for (int s = 0; s < OSLICE; s++) {
            const int d = d0 + st * OSLICE + s;
            const float* P = sm[b] + s * (OHALO * WW);

            float4 v = *(const float4*)&P[rB + x0];

            if (d != 0) {
                const float4 A0 = *(const float4*)&P[rA + x0];
                const float4 D0 = *(const float4*)&P[rD + x0];
                const float  AL = firstx ? A0.x : P[rA + x0 - 1];
                const float  DL = firstx ? D0.x : P[rD + x0 - 1];
                float2 A1, D1;
                if (!lastx) {
                    A1 = *(const float2*)&P[rA + x0 + 4];
                    D1 = *(const float2*)&P[rD + x0 + 4];
                } else {                        // cols 64,65 clamp to 63
                    A1 = make_float2(A0.w, A0.w);
                    D1 = make_float2(D0.w, D0.w);
                }
                // dx=-1 values: AL, A0.x, A0.y, A0.z ; dx=+2: A0.z, A0.w, A1.x, A1.y
                v.x = fmaf(w0.x, AL,   fmaf(w1.x, A0.z, fmaf(w2.x, DL,   fmaf(w3.x, D0.z, v.x))));
                v.y = fmaf(w0.y, A0.x, fmaf(w1.y, A0.w, fmaf(w2.y, D0.x, fmaf(w3.y, D0.w, v.y))));
                v.z = fmaf(w0.z, A0.y, fmaf(w1.z, A1.x, fmaf(w2.z, D0.y, fmaf(w3.z, D1.x, v.z))));
                v.w = fmaf(w0.w, A0.z, fmaf(w1.w, A1.y, fmaf(w2.w, D0.z, fmaf(w3.w, D1.y, v.w))));
            }

            v.x = cond.x != 0.f ? v.x : 0.f;
            v.y = cond.y != 0.f ? v.y : 0.f;
            v.z = cond.z != 0.f ? v.z : 0.f;
            v.w = cond.w != 0.f ? v.w : 0.f;

            *(float4*)&outB[(size_t)(st * OSLICE + s) * HW] = v;
        }
        __syncthreads();
    }
}

// ---------------------------------------------------------------------------
extern "C" void kernel_launch(void* const* d_in, const int* in_sizes, int n_in,
                              void* d_out, int out_size) {
    const float* cur  = (const float*)d_in[0];
    const float* prev = (const float*)d_in[1];
    const float* mem  = (const float*)d_in[2];
    float* out = (float*)d_out;

    k_partial<<<dim3(HH / TY, DCH, NB), dim3(32, TY)>>>(cur, prev, mem);
    k_reduce<<<(NB * 14 * HW / 4) / 256, 256>>>();
    k_weights<<<dim3(HH / TY, NB), dim3(WW, TY)>>>();
    k_output<<<dim3(HH / OTY, ODC, NB), dim3(16, OTY)>>>(mem, out);
}

// round 11
// speedup vs baseline: 1.4732x; 1.0804x over previous
#include <cuda_runtime.h>

#define NB   4
#define DC   256
#define HH   64
#define WW   64
#define HW   4096
#define DCH  16       // chunks over D (pass 1)
#define DPER 16       // D per chunk (pass 1)
#define NOFF 12
#define TY   4        // rows per tile (pass 1 / pass 2b)
#define HALO 7        // TY + 3 halo rows
#define DSLICE 4      // d-slices per pipeline stage (pass 1)
#define ODC  32       // d-chunks for k_output
#define ODPER 8       // d per k_output block
#define OSLICE 4      // d-slices per k_output stage
#define OTY  8        // rows per k_output tile
#define OHALO 11      // OTY + 3

// offset order: 3x3 window row-major (idx 4 = (0,0)), then (-1,2),(2,-1),(2,2).
__device__ __constant__ int c_dy[NOFF] = {-1,-1,-1, 0,0,0, 1,1,1, -1, 2, 2};
__device__ __constant__ int c_dx[NOFF] = {-1, 0, 1,-1,0,1,-1,0,1,  2,-1, 2};

// scratch (no allocations allowed)
__device__ __align__(16) float g_part[(size_t)NB * DCH * 14 * HW];   // 14.7 MB
__device__ __align__(16) float g_red[(size_t)NB * 14 * HW];
__device__ __align__(16) float g_w0[NB * HW];
__device__ __align__(16) float g_w1[NB * HW];
__device__ __align__(16) float g_w2[NB * HW];
__device__ __align__(16) float g_w3[NB * HW];
__device__ __align__(16) float g_cond[NB * HW];

__device__ __forceinline__ int iclamp(int v, int lo, int hi) {
    return v < lo ? lo : (v > hi ? hi : v);
}

__device__ __forceinline__ void cp_async16(void* dst, const void* src) {
    unsigned int da = (unsigned int)__cvta_generic_to_shared(dst);
    asm volatile("cp.async.cg.shared.global [%0], [%1], 16;" :: "r"(da), "l"(src));
}
__device__ __forceinline__ void cp_commit() {
    asm volatile("cp.async.commit_group;");
}
template <int N>
__device__ __forceinline__ void cp_wait() {
    asm volatile("cp.async.wait_group %0;" :: "n"(N));
}
__device__ __forceinline__ void prefetch_l2(const void* p) {
    asm volatile("prefetch.global.L2 [%0];" :: "l"(p));
}
// PDL: wait until the upstream grid's writes are visible (no-op if launched
// without the PDL attribute).
__device__ __forceinline__ void pdl_wait() {
    asm volatile("griddepcontrol.wait;" ::: "memory");
}
__device__ __forceinline__ void pdl_trigger() {
    asm volatile("griddepcontrol.launch_dependents;" ::: "memory");
}

#define PREV_F (DSLICE * HALO * WW)     // 1792 floats
#define CUR_F  (DSLICE * TY * WW)       // 1024 floats
#define TOT_Q  ((PREV_F + CUR_F) / 4)   // 704 float4 per buffer

// ---------------------------------------------------------------------------
// Pass 1: cp.async double-buffered, 2 pixels/thread with vector LDS.
// grid (16 ytiles, 16 dchunks, 4 batch) = 1024 blocks, block (32,4) = 128 thr
// ---------------------------------------------------------------------------
__global__ __launch_bounds__(128) void k_partial(const float* __restrict__ cur,
                                                 const float* __restrict__ prev,
                                                 const float* __restrict__ mem) {
    __shared__ float sp[2][PREV_F];
    __shared__ float sc[2][CUR_F];

    const int tx  = threadIdx.x;           // 0..31 -> pixels 2tx, 2tx+1
    const int ty  = threadIdx.y;           // 0..3
    const int y0  = blockIdx.x * TY;
    const int dch = blockIdx.y;
    const int n   = blockIdx.z;
    const int tid = ty * 32 + tx;
    const int x0  = tx * 2;

    const float* curB  = cur  + (size_t)n * DC * HW;
    const float* prevB = prev + (size_t)n * DC * HW;
    const int d0 = dch * DPER;

    auto stage = [&](int b, int dbase) {
#pragma unroll
        for (int j = 0; j < 6; j++) {
            const int i = tid + j * 128;
            if (i < PREV_F / 4) {
                const int s  = i / (HALO * 16);
                const int rm = i - s * (HALO * 16);
                const int r  = rm >> 4;
                const int c4 = rm & 15;
                const int gr = iclamp(y0 - 1 + r, 0, HH - 1);
                cp_async16(&sp[b][s * (HALO * WW) + r * WW + c4 * 4],
                           prevB + (size_t)(dbase + s) * HW + gr * WW + c4 * 4);
            } else if (i < TOT_Q) {
                const int k  = i - PREV_F / 4;
                const int s  = k >> 6;
                const int rm = k & 63;
                const int r  = rm >> 4;
                const int c4 = rm & 15;
                cp_async16(&sc[b][s * (TY * WW) + r * WW + c4 * 4],
                           curB + (size_t)(dbase + s) * HW + (y0 + r) * WW + c4 * 4);
            }
        }
        cp_commit();
    };

    stage(0, d0);

    // L2-prefetch mem so k_output hits L2 (one 128B line per thread)
    {
        const float* memB = mem + (size_t)n * DC * HW;
        const int dd   = tid >> 3;
        const int r    = (tid >> 1) & 3;
        const int half = tid & 1;
        prefetch_l2(memB + (size_t)(d0 + dd) * HW + (y0 + r) * WW + half * 32);
    }

    const int rA = (ty    ) * WW;
    const int rB = (ty + 1) * WW;
    const int rC = (ty + 2) * WW;
    const int rD = (ty + 3) * WW;
    const int xl  = x0 == 0 ? 0 : x0 - 1;
    const int xr2 = x0 + 2 > WW - 1 ? WW - 1 : x0 + 2;
    const bool lastx = (tx == 31);

    float2 acc[14];
#pragma unroll
    for (int k = 0; k < 14; k++) acc[k] = make_float2(0.f, 0.f);

#pragma unroll 1
    for (int d4 = 0; d4 < DPER / DSLICE; d4++) {
        if (d4 + 1 < DPER / DSLICE) {
            stage((d4 + 1) & 1, d0 + (d4 + 1) * DSLICE);
            cp_wait<1>();
        } else {
            cp_wait<0>();
        }
        __syncthreads();

        const int b = d4 & 1;
#pragma unroll
        for (int s = 0; s < DSLICE; s++) {
            const float* P = sp[b] + s * (HALO * WW);
            const float2 c2 = *(const float2*)&sc[b][s * (TY * WW) + ty * WW + x0];

            const float2 A0 = *(const float2*)&P[rA + x0];
            const float2 B0 = *(const float2*)&P[rB + x0];
            const float2 C0 = *(const float2*)&P[rC + x0];
            const float2 D0 = *(const float2*)&P[rD + x0];
            const float  AL = P[rA + xl];
            const float  BL = P[rB + xl];
            const float  CL = P[rC + xl];
            const float  DL = P[rD + xl];
            const float2 A1 = lastx ? make_float2(A0.y, A0.y)
                                    : *(const float2*)&P[rA + x0 + 2];
            const float2 D1 = lastx ? make_float2(D0.y, D0.y)
                                    : *(const float2*)&P[rD + x0 + 2];
            const float  B2 = P[rB + xr2];
            const float  C2 = P[rC + xr2];

            const float c0 = c2.x, c1 = c2.y;
            acc[0].x  = fmaf(c0, AL,   acc[0].x);   acc[0].y  = fmaf(c1, A0.x, acc[0].y);
            acc[1].x  = fmaf(c0, A0.x, acc[1].x);   acc[1].y  = fmaf(c1, A0.y, acc[1].y);
            acc[2].x  = fmaf(c0, A0.y, acc[2].x);   acc[2].y  = fmaf(c1, A1.x, acc[2].y);
            acc[3].x  = fmaf(c0, BL,   acc[3].x);   acc[3].y  = fmaf(c1, B0.x, acc[3].y);
            acc[4].x  = fmaf(c0, B0.x, acc[4].x);   acc[4].y  = fmaf(c1, B0.y, acc[4].y);
            acc[5].x  = fmaf(c0, B0.y, acc[5].x);   acc[5].y  = fmaf(c1, B2,   acc[5].y);
            acc[6].x  = fmaf(c0, CL,   acc[6].x);   acc[6].y  = fmaf(c1, C0.x, acc[6].y);
            acc[7].x  = fmaf(c0, C0.x, acc[7].x);   acc[7].y  = fmaf(c1, C0.y, acc[7].y);
            acc[8].x  = fmaf(c0, C0.y, acc[8].x);   acc[8].y  = fmaf(c1, C2,   acc[8].y);
            acc[9].x  = fmaf(c0, A1.x, acc[9].x);   acc[9].y  = fmaf(c1, A1.y, acc[9].y);
            acc[10].x = fmaf(c0, DL,   acc[10].x);  acc[10].y = fmaf(c1, D0.x, acc[10].y);
            acc[11].x = fmaf(c0, D1.x, acc[11].x);  acc[11].y = fmaf(c1, D1.y, acc[11].y);
            acc[12].x = fmaf(c0, c0,   acc[12].x);  acc[12].y = fmaf(c1, c1,   acc[12].y);
            acc[13].x = fmaf(B0.x, B0.x, acc[13].x);
            acc[13].y = fmaf(B0.y, B0.y, acc[13].y);
        }
        __syncthreads();
    }

    const int pix = (y0 + ty) * WW + x0;
    float* o = g_part + (size_t)(n * DCH + dch) * 14 * HW + pix;
#pragma unroll
    for (int k = 0; k < 14; k++) *(float2*)&o[(size_t)k * HW] = acc[k];
    pdl_trigger();
}

// ---------------------------------------------------------------------------
// Pass 2a: reduce 16 D-chunks, float4-coalesced. 57344 threads.
// ---------------------------------------------------------------------------
__global__ __launch_bounds__(256) void k_reduce() {
    const int t    = blockIdx.x * blockDim.x + threadIdx.x;
    const int n    = t / (14 * 1024);
    const int r    = t - n * (14 * 1024);
    const int slot = r >> 10;
    const int p4   = (r & 1023) << 2;

    pdl_wait();   // g_part ready

    float4 a = make_float4(0.f, 0.f, 0.f, 0.f);
#pragma unroll
    for (int c = 0; c < DCH; c++) {
        const float4 v = *(const float4*)&g_part[(((size_t)(n * DCH + c)) * 14 + slot) * HW + p4];
        a.x += v.x; a.y += v.y; a.z += v.z; a.w += v.w;
    }
    *(float4*)&g_red[((size_t)n * 14 + slot) * HW + p4] = a;
    pdl_trigger();
}

// ---------------------------------------------------------------------------
// Pass 2b: cosine affinity -> cond + 4 agg weights (g_red L2-hot).
// ---------------------------------------------------------------------------
__global__ __launch_bounds__(256) void k_weights() {
    __shared__ float s_pn[HALO * WW];

    const int x   = threadIdx.x;
    const int ty  = threadIdx.y;
    const int y0  = blockIdx.x * TY;
    const int n   = blockIdx.y;
    const int tid = ty * WW + x;

    const float* base = g_red + (size_t)n * 14 * HW;

    pdl_wait();   // g_red ready

    for (int i = tid; i < HALO * WW; i += 256) {
        const int r  = i >> 6;
        const int cc = i & (WW - 1);
        const int gr = iclamp(y0 - 1 + r, 0, HH - 1);
        s_pn[i] = sqrtf(base[(size_t)13 * HW + gr * WW + cc]) + 1e-8f;
    }
    __syncthreads();

    const int y   = y0 + ty;
    const int pix = y * WW + x;

    float acc[13];
#pragma unroll
    for (int k = 0; k < 13; k++) acc[k] = base[(size_t)k * HW + pix];

    const float invcn = 1.f / (sqrtf(acc[12]) + 1e-8f);

    float aff[NOFF];
#pragma unroll
    for (int k = 0; k < NOFF; k++) {
        const int py = y + c_dy[k];
        const int px = x + c_dx[k];
        const bool valid = (py >= 0) & (py < HH) & (px >= 0) & (px < WW);
        const int lr = ty + c_dy[k] + 1;
        const int lc = iclamp(px, 0, WW - 1);
        const float pn = s_pn[lr * WW + lc];
        float a = acc[k] * invcn / pn;
        a = fmaxf(a, 0.f);
        aff[k] = valid ? a : 0.f;
    }

    float mass = 0.f;
#pragma unroll
    for (int k = 0; k < 9; k++) mass += aff[k];

    const bool  cond = (mass > -10.f) && (mass < 10.f);
    const float inv  = 1.f / (mass > 0.f ? mass : 1.f);

    const int t = n * HW + pix;
    g_w0[t]   = aff[0]  > 0.f ? aff[0]  * inv : 0.f;  // (-1,-1)
    g_w1[t]   = aff[9]  > 0.f ? aff[9]  * inv : 0.f;  // (-1,+2)
    g_w2[t]   = aff[10] > 0.f ? aff[10] * inv : 0.f;  // (+2,-1)
    g_w3[t]   = aff[11] > 0.f ? aff[11] * inv : 0.f;  // (+2,+2)
    g_cond[t] = cond ? 1.f : 0.f;
    pdl_trigger();
}

// ---------------------------------------------------------------------------
// Pass 3: 4 pixels/thread, float4 LDS + STG.128, cp.async double-buffered.
// PDL: first mem stage + setup run BEFORE the dependency wait (mem is an
// external input); only the weight loads need k_weights' output.
// grid (8 ytiles, 32 dchunks, 4 batch) = 1024 blocks, block (16,8) = 128 thr
// ---------------------------------------------------------------------------
#define OMEM_F (OSLICE * OHALO * WW)     // 2816 floats per buffer (11.3 KB)

__global__ __launch_bounds__(128) void k_output(const float* __restrict__ mem,
                                                float* __restrict__ out) {
    __shared__ float sm[2][OMEM_F];      // 22.5 KB

    const int tx  = threadIdx.x;            // 0..15 -> pixels 4tx..4tx+3
    const int ty  = threadIdx.y;            // 0..7
    const int y0  = blockIdx.x * OTY;
    const int dch = blockIdx.y;
    const int n   = blockIdx.z;
    const int tid = ty * 16 + tx;           // 0..127
    const int x0  = tx * 4;
    const int d0  = dch * ODPER;

    const float* memB = mem + (size_t)n * DC * HW;

    auto stage = [&](int b, int dbase) {
#pragma unroll
        for (int j = 0; j < 6; j++) {          // 704 float4 / 128 threads
            const int i = tid + j * 128;
            if (i < OMEM_F / 4) {
                const int s  = i / (OHALO * 16);
                const int rm = i - s * (OHALO * 16);
                const int r  = rm >> 4;
                const int c4 = rm & 15;
                const int gr = iclamp(y0 - 1 + r, 0, HH - 1);
                cp_async16(&sm[b][s * (OHALO * WW) + r * WW + c4 * 4],
                           memB + (size_t)(dbase + s) * HW + gr * WW + c4 * 4);
            }
        }
        cp_commit();
    };

    // ---- pre-dependency prologue: stage buffer 0 from mem (input) ----
    stage(0, d0);
    // also stage buffer 1 early (still only mem)
    stage(1, d0 + OSLICE);

    const int y   = y0 + ty;
    const int np  = n * HW + y * WW + x0;
    const int rA = (ty    ) * WW;   // y-1
    const int rB = (ty + 1) * WW;   // y
    const int rD = (ty + 3) * WW;   // y+2
    const bool firstx = (tx == 0);
    const bool lastx  = (tx == 15);

    // ---- wait for k_weights' output, then load weights ----
    pdl_wait();

    const float4 cond = *(const float4*)&g_cond[np];
    const float4 w0   = *(const float4*)&g_w0[np];
    const float4 w1   = *(const float4*)&g_w1[np];
    const float4 w2   = *(const float4*)&g_w2[np];
    const float4 w3   = *(const float4*)&g_w3[np];

    float* outB = out + ((size_t)n * DC + d0) * HW + y * WW + x0;

#pragma unroll 1
    for (int st = 0; st < ODPER / OSLICE; st++) {
        if (st + 1 < ODPER / OSLICE) {
            cp_wait<1>();          // buffer st ready (both were committed up front)
        } else {
            cp_wait<0>();
        }
        __syncthreads();

        const int b = st & 1;
#pragma unroll
        for (int s = 0; s < OSLICE; s++) {
            const int d = d0 + st * OSLICE + s;
            const float* P = sm[b] + s * (OHALO * WW);

            float4 v = *(const float4*)&P[rB + x0];

            if (d != 0) {
                const float4 A0 = *(const float4*)&P[rA + x0];
                const float4 D0 = *(const float4*)&P[rD + x0];
                const float  AL = firstx ? A0.x : P[rA + x0 - 1];
                const float  DL = firstx ? D0.x : P[rD + x0 - 1];
                float2 A1, D1;
                if (!lastx) {
                    A1 = *(const float2*)&P[rA + x0 + 4];
                    D1 = *(const float2*)&P[rD + x0 + 4];
                } else {                        // cols 64,65 clamp to 63
                    A1 = make_float2(A0.w, A0.w);
                    D1 = make_float2(D0.w, D0.w);
                }
                v.x = fmaf(w0.x, AL,   fmaf(w1.x, A0.z, fmaf(w2.x, DL,   fmaf(w3.x, D0.z, v.x))));
                v.y = fmaf(w0.y, A0.x, fmaf(w1.y, A0.w, fmaf(w2.y, D0.x, fmaf(w3.y, D0.w, v.y))));
                v.z = fmaf(w0.z, A0.y, fmaf(w1.z, A1.x, fmaf(w2.z, D0.y, fmaf(w3.z, D1.x, v.z))));
                v.w = fmaf(w0.w, A0.z, fmaf(w1.w, A1.y, fmaf(w2.w, D0.z, fmaf(w3.w, D1.y, v.w))));
            }

            v.x = cond.x != 0.f ? v.x : 0.f;
            v.y = cond.y != 0.f ? v.y : 0.f;
            v.z = cond.z != 0.f ? v.z : 0.f;
            v.w = cond.w != 0.f ? v.w : 0.f;

            *(float4*)&outB[(size_t)(st * OSLICE + s) * HW] = v;
        }
        __syncthreads();
    }
}

// ---------------------------------------------------------------------------
static inline void launch_pdl(const void* func, dim3 grid, dim3 block, void** args) {
    cudaLaunchConfig_t cfg = {};
    cfg.gridDim  = grid;
    cfg.blockDim = block;
    cfg.dynamicSmemBytes = 0;
    cfg.stream = 0;
    cudaLaunchAttribute attr[1];
    attr[0].id = cudaLaunchAttributeProgrammaticStreamSerialization;
    attr[0].val.programmaticStreamSerializationAllowed = 1;
    cfg.attrs = attr;
    cfg.numAttrs = 1;
    cudaLaunchKernelExC(&cfg, func, args);
}

extern "C" void kernel_launch(void* const* d_in, const int* in_sizes, int n_in,
                              void* d_out, int out_size) {
    const float* cur  = (const float*)d_in[0];
    const float* prev = (const float*)d_in[1];
    const float* mem  = (const float*)d_in[2];
    float* out = (float*)d_out;

    k_partial<<<dim3(HH / TY, DCH, NB), dim3(32, TY)>>>(cur, prev, mem);

    {
        void* args[] = {};
        launch_pdl((const void*)k_reduce,
                   dim3((NB * 14 * HW / 4) / 256), dim3(256), args);
    }
    {
        void* args[] = {};
        launch_pdl((const void*)k_weights,
                   dim3(HH / TY, NB), dim3(WW, TY), args);
    }
    {
        void* args[] = { (void*)&mem, (void*)&out };
        launch_pdl((const void*)k_output,
                   dim3(HH / OTY, ODC, NB), dim3(16, OTY), args);
    }
}